// round 2
// baseline (speedup 1.0000x reference)
#include <cuda_runtime.h>
#include <math.h>

// ---------------- shapes ----------------
// B=32, N=2048, DIM_IN=128, DIM_OUT=256, DIM_CTX=259
#define NB   32
#define NN   2048
#define CIN  128
#define COUT 256
#define CTXD 259

// ---------------- device scratch ----------------
__device__ float d_gate[NB * COUT];          // sigmoid gate per (b, o)
__device__ float d_hbias[NB * COUT];         // hyper bias per (b, o)
__device__ float d_M[NB * COUT * COUT];      // (I - attention[b]) row-major [o'][o]
__device__ float d_C[NB * COUT * COUT];      // (I-A) @ W_tc^T
__device__ float d_D[NB * CIN * COUT];       // W_layer^T @ C[b]   [i][e]
__device__ float d_bc[NB * COUT];            // b_layer @ C[b] + b_tc
__device__ float d_WT[CIN * COUT];           // W_layer^T  [i][o]
__device__ float d_WtcT[COUT * COUT];        // W_tc^T     [o][e]
__device__ float d_Y[NB * NN * 512];         // [x1 | t] per batch, stride 512 (134 MB)
__device__ float d_mean[NN];
__device__ float d_rstd[NN];

// ---------------- transpose helpers ----------------
__global__ void k_transpose(const float* __restrict__ Wl, const float* __restrict__ Wtc) {
    int tid = blockIdx.x * 256 + threadIdx.x;
    if (blockIdx.y == 0) {
        // WT[i][o] = W_layer[o][i]   (128 x 256)
        if (tid < CIN * COUT) {
            int i = tid >> 8, o = tid & 255;
            d_WT[tid] = Wl[o * CIN + i];
        }
    } else {
        // WtcT[o][e] = W_tc[e][o]    (256 x 256)
        if (tid < COUT * COUT) {
            int o = tid >> 8, e = tid & 255;
            d_WtcT[tid] = Wtc[e * COUT + o];
        }
    }
}

// ---------------- per-batch: gate, hbias, k, v, attention, M = I - A ----------------
__global__ __launch_bounds__(256) void k_s1(
    const float* __restrict__ ctx, const float* __restrict__ Wg,
    const float* __restrict__ bg,  const float* __restrict__ Whb,
    const float* __restrict__ Wk,  const float* __restrict__ Wv)
{
    int b = blockIdx.x;
    int tid = threadIdx.x;
    __shared__ float cs[CTXD];
    __shared__ float ks[COUT], vs[COUT], ms[COUT], invr[COUT];
    __shared__ float vmm[2];

    for (int i = tid; i < CTXD; i += 256) cs[i] = ctx[b * CTXD + i];
    __syncthreads();

    int warp = tid >> 5, lane = tid & 31;
    // warp-per-output dot products (coalesced along c)
    for (int o = warp; o < COUT; o += 8) {
        float kk = 0.f, vv = 0.f, gg = 0.f, hb = 0.f;
        for (int c = lane; c < 256; c += 32) {
            float cv = cs[c];
            kk = fmaf(cv, Wk[o * 256 + c], kk);
            vv = fmaf(cv, Wv[o * 256 + c], vv);
        }
        for (int c = lane; c < CTXD; c += 32) {
            float cv = cs[c];
            gg = fmaf(cv, Wg[o * CTXD + c], gg);
            hb = fmaf(cv, Whb[o * CTXD + c], hb);
        }
        #pragma unroll
        for (int s = 16; s; s >>= 1) {
            kk += __shfl_xor_sync(0xffffffffu, kk, s);
            vv += __shfl_xor_sync(0xffffffffu, vv, s);
            gg += __shfl_xor_sync(0xffffffffu, gg, s);
            hb += __shfl_xor_sync(0xffffffffu, hb, s);
        }
        if (lane == 0) {
            ks[o] = kk; vs[o] = vv;
            float z = gg + bg[o];
            d_gate[b * COUT + o]  = 1.f / (1.f + expf(-z));
            d_hbias[b * COUT + o] = hb;
        }
    }
    __syncthreads();

    if (tid == 0) {
        float mx = vs[0], mn = vs[0];
        for (int i = 1; i < COUT; i++) { mx = fmaxf(mx, vs[i]); mn = fminf(mn, vs[i]); }
        vmm[0] = mx; vmm[1] = mn;
    }
    __syncthreads();

    // row softmax prep: thread tid owns row o = tid
    {
        float kk = ks[tid];
        float m = (kk >= 0.f) ? kk * vmm[0] : kk * vmm[1];
        float r = 0.f;
        for (int e = 0; e < COUT; e++) r += expf(fmaf(kk, vs[e], -m));
        ms[tid] = m;
        invr[tid] = 1.f / r;
    }
    __syncthreads();

    // column pass: thread tid owns column e = tid.
    // Stage row-softmaxed values, accumulate column sum, then rescale + (I - A).
    float* Mb = d_M + b * (COUT * COUT);
    {
        float ve = vs[tid];
        float csum = 0.f;
        for (int o = 0; o < COUT; o++) {
            float val = expf(fmaf(ks[o], ve, -ms[o])) * invr[o];
            Mb[o * COUT + tid] = val;      // coalesced across threads
            csum += val;
        }
        float cinv = 1.f / (1e-9f + csum);
        for (int o = 0; o < COUT; o++) {
            float a = Mb[o * COUT + tid] * cinv;
            Mb[o * COUT + tid] = (o == tid ? 1.f : 0.f) - a;
        }
    }
}

// ---------------- shared 64x64x(K) fp32 GEMM tile ----------------
// A: [m][k] row-major, lda;  B: [k][n] row-major, ldb;  C: [m][n], ldc.
// Pointers already offset to tile origin. biasp: 64 per-column biases or null.
__device__ __forceinline__ void gemm64(
    const float* __restrict__ A, int lda,
    const float* __restrict__ Bp, int ldb,
    float* __restrict__ Cp, int ldc,
    const float* __restrict__ biasp, int K)
{
    __shared__ float As[64][64];
    __shared__ float Bs[64][64];
    int tx = threadIdx.x, ty = threadIdx.y;
    int tid = ty * 16 + tx;

    float acc[4][4];
    #pragma unroll
    for (int i = 0; i < 4; i++)
        #pragma unroll
        for (int j = 0; j < 4; j++) acc[i][j] = 0.f;

    for (int k0 = 0; k0 < K; k0 += 64) {
        #pragma unroll
        for (int t = tid; t < 1024; t += 256) {
            int m = t >> 4, k4 = (t & 15) << 2;
            float4 v = *(const float4*)(A + m * lda + k0 + k4);
            *(float4*)&As[m][k4] = v;
        }
        #pragma unroll
        for (int t = tid; t < 1024; t += 256) {
            int k = t >> 4, n4 = (t & 15) << 2;
            float4 v = *(const float4*)(Bp + (k0 + k) * ldb + n4);
            *(float4*)&Bs[k][n4] = v;
        }
        __syncthreads();
        #pragma unroll 16
        for (int k = 0; k < 64; k++) {
            float4 bv = *(const float4*)&Bs[k][tx << 2];
            float a0 = As[(ty << 2) + 0][k];
            float a1 = As[(ty << 2) + 1][k];
            float a2 = As[(ty << 2) + 2][k];
            float a3 = As[(ty << 2) + 3][k];
            acc[0][0] = fmaf(a0, bv.x, acc[0][0]); acc[0][1] = fmaf(a0, bv.y, acc[0][1]);
            acc[0][2] = fmaf(a0, bv.z, acc[0][2]); acc[0][3] = fmaf(a0, bv.w, acc[0][3]);
            acc[1][0] = fmaf(a1, bv.x, acc[1][0]); acc[1][1] = fmaf(a1, bv.y, acc[1][1]);
            acc[1][2] = fmaf(a1, bv.z, acc[1][2]); acc[1][3] = fmaf(a1, bv.w, acc[1][3]);
            acc[2][0] = fmaf(a2, bv.x, acc[2][0]); acc[2][1] = fmaf(a2, bv.y, acc[2][1]);
            acc[2][2] = fmaf(a2, bv.z, acc[2][2]); acc[2][3] = fmaf(a2, bv.w, acc[2][3]);
            acc[3][0] = fmaf(a3, bv.x, acc[3][0]); acc[3][1] = fmaf(a3, bv.y, acc[3][1]);
            acc[3][2] = fmaf(a3, bv.z, acc[3][2]); acc[3][3] = fmaf(a3, bv.w, acc[3][3]);
        }
        __syncthreads();
    }

    float b0 = 0.f, b1 = 0.f, b2 = 0.f, b3 = 0.f;
    if (biasp) {
        b0 = biasp[(tx << 2) + 0]; b1 = biasp[(tx << 2) + 1];
        b2 = biasp[(tx << 2) + 2]; b3 = biasp[(tx << 2) + 3];
    }
    #pragma unroll
    for (int i = 0; i < 4; i++) {
        float4 o;
        o.x = acc[i][0] + b0; o.y = acc[i][1] + b1;
        o.z = acc[i][2] + b2; o.w = acc[i][3] + b3;
        *(float4*)(Cp + ((ty << 2) + i) * ldc + (tx << 2)) = o;
    }
}

// C[b] = M[b] @ WtcT   (256x256x256 per batch)
__global__ __launch_bounds__(256) void k_gemm_C() {
    int b = blockIdx.z;
    const float* A  = d_M + b * (COUT * COUT) + blockIdx.x * 64 * COUT;
    const float* Bp = d_WtcT + blockIdx.y * 64;
    float* Cp = d_C + b * (COUT * COUT) + blockIdx.x * 64 * COUT + blockIdx.y * 64;
    gemm64(A, COUT, Bp, COUT, Cp, COUT, nullptr, COUT);
}

// D[b] = WT @ C[b]     (128x256x256 per batch)
__global__ __launch_bounds__(256) void k_gemm_D() {
    int b = blockIdx.z;
    const float* A  = d_WT + blockIdx.x * 64 * COUT;
    const float* Bp = d_C + b * (COUT * COUT) + blockIdx.y * 64;
    float* Cp = d_D + b * (CIN * COUT) + blockIdx.x * 64 * COUT + blockIdx.y * 64;
    gemm64(A, COUT, Bp, COUT, Cp, COUT, nullptr, COUT);
}

// bc[b][e] = sum_o b_layer[o] * C[b][o][e] + b_tc[e]
__global__ void k_bc(const float* __restrict__ b_layer, const float* __restrict__ b_tc) {
    int b = blockIdx.x, e = threadIdx.x;
    float s = b_tc[e];
    const float* Cb = d_C + b * (COUT * COUT);
    for (int o = 0; o < COUT; o++) s = fmaf(b_layer[o], Cb[o * COUT + e], s);
    d_bc[b * COUT + e] = s;
}

// main fused GEMM: Y[b] = x[b] @ [W_layer^T | D[b]] + [b_layer | bc[b]]
__global__ __launch_bounds__(256) void k_gemm_main(
    const float* __restrict__ x, const float* __restrict__ b_layer)
{
    int b = blockIdx.z;
    int by = blockIdx.y;
    int row0 = blockIdx.x * 64;
    const float* A = x + b * (NN * CIN) + row0 * CIN;
    const float* Bp;
    const float* biasp;
    if (by < 4) { Bp = d_WT + by * 64;                         biasp = b_layer + by * 64; }
    else        { Bp = d_D + b * (CIN * COUT) + (by - 4) * 64; biasp = d_bc + b * COUT + (by - 4) * 64; }
    float* Cp = d_Y + b * (NN * 512) + row0 * 512 + by * 64;
    gemm64(A, CIN, Bp, COUT, Cp, 512, biasp, CIN);
}

// BN stats over (b, e) per n
__global__ void k_bnstats() {
    int n = blockIdx.x, e = threadIdx.x;
    const float* base = d_Y + n * 512 + 256 + e;
    float s = 0.f, q = 0.f;
    #pragma unroll
    for (int b = 0; b < NB; b++) {
        float v = base[b * (NN * 512)];
        s += v; q = fmaf(v, v, q);
    }
    __shared__ float ss[256], sq[256];
    ss[e] = s; sq[e] = q;
    __syncthreads();
    for (int st = 128; st; st >>= 1) {
        if (e < st) { ss[e] += ss[e + st]; sq[e] += sq[e + st]; }
        __syncthreads();
    }
    if (e == 0) {
        float mean = ss[0] * (1.f / 8192.f);
        float var  = sq[0] * (1.f / 8192.f) - mean * mean;
        d_mean[n] = mean;
        d_rstd[n] = rsqrtf(var + 1e-5f);
    }
}

// epilogue: out = (x1 + relu(bn(t))) * gate + hbias
__global__ void k_final(const float* __restrict__ gamma, const float* __restrict__ beta,
                        float* __restrict__ out)
{
    int idx = blockIdx.x * 256 + threadIdx.x;
    int e = idx & 255;
    int n = (idx >> 8) & (NN - 1);
    int b = idx >> 19;
    int ybase = b * (NN * 512) + n * 512;
    float x1 = d_Y[ybase + e];
    float tv = d_Y[ybase + 256 + e];
    float bn = fmaf((tv - d_mean[n]) * d_rstd[n], gamma[n], beta[n]);
    bn = fmaxf(bn, 0.f);
    out[idx] = fmaf(x1 + bn, d_gate[b * COUT + e], d_hbias[b * COUT + e]);
}

// ---------------- launch ----------------
extern "C" void kernel_launch(void* const* d_in, const int* in_sizes, int n_in,
                              void* d_out, int out_size)
{
    (void)in_sizes; (void)n_in; (void)out_size;
    const float* ctx     = (const float*)d_in[0];
    const float* x       = (const float*)d_in[1];
    const float* W_layer = (const float*)d_in[2];
    const float* b_layer = (const float*)d_in[3];
    const float* W_hbias = (const float*)d_in[4];
    const float* W_gate  = (const float*)d_in[5];
    const float* b_gate  = (const float*)d_in[6];
    const float* W_k     = (const float*)d_in[7];
    const float* W_v     = (const float*)d_in[8];
    const float* W_tc    = (const float*)d_in[9];
    const float* b_tc    = (const float*)d_in[10];
    const float* gamma   = (const float*)d_in[11];
    const float* beta    = (const float*)d_in[12];
    float* out = (float*)d_out;

    dim3 blk(16, 16);
    k_transpose<<<dim3(256, 2), 256>>>(W_layer, W_tc);
    k_s1<<<NB, 256>>>(ctx, W_gate, b_gate, W_hbias, W_k, W_v);
    k_gemm_C<<<dim3(4, 4, NB), blk>>>();
    k_gemm_D<<<dim3(2, 4, NB), blk>>>();
    k_bc<<<NB, 256>>>(b_layer, b_tc);
    k_gemm_main<<<dim3(NN / 64, 8, NB), blk>>>(x, b_layer);
    k_bnstats<<<NN, 256>>>();
    k_final<<<(NB * NN * COUT) / 256, 256>>>(gamma, beta, out);
}

// round 4
// speedup vs baseline: 1.1057x; 1.1057x over previous
#include <cuda_runtime.h>
#include <math.h>

// ---------------- shapes ----------------
// B=32, N=2048, DIM_IN=128, DIM_OUT=256, DIM_CTX=259
#define NB   32
#define NN   2048
#define CIN  128
#define COUT 256
#define CTXD 259

// ---------------- device scratch ----------------
__device__ float d_gate[NB * COUT];
__device__ float d_hbias[NB * COUT];
__device__ float d_MT[NB * COUT * COUT];     // (I - A)^T, stored [k=e][m=o]  (k-major A for C-gemm)
__device__ float d_C[NB * COUT * COUT];      // (I-A) @ W_tc^T, row-major [o][e]
__device__ float d_D[NB * CIN * COUT];       // W_layer^T @ C[b], row-major [i][e]
__device__ float d_bc[NB * COUT];            // b_layer @ C[b] + b_tc
__device__ float d_WT[CIN * COUT];           // W_layer^T  [i][o]
__device__ float d_WtcT[COUT * COUT];        // W_tc^T     [e][e']
__device__ float d_xT[NB * CIN * NN];        // x transposed per batch: [b][k=i][m=n]
__device__ float d_Y[NB * NN * 512];         // [x1 | t] per batch row, stride 512
__device__ float d_mean[NN];
__device__ float d_rstd[NN];

// ---------------- f32x2 packed-FMA helpers ----------------
__device__ __forceinline__ double ffma2(double a, double b, double c) {
    double d;
    asm("fma.rn.f32x2 %0, %1, %2, %3;" : "=d"(d) : "d"(a), "d"(b), "d"(c));
    return d;
}
__device__ __forceinline__ double pack2(float x) {
    double d;
    asm("mov.b64 %0, {%1, %1};" : "=d"(d) : "f"(x));
    return d;
}
__device__ __forceinline__ void unpack2(double d, float& lo, float& hi) {
    asm("mov.b64 {%0, %1}, %2;" : "=f"(lo), "=f"(hi) : "d"(d));
}

// ---------------- cp.async helpers ----------------
__device__ __forceinline__ void cp16(float* smem_dst, const float* gmem_src) {
    unsigned sa = (unsigned)__cvta_generic_to_shared(smem_dst);
    asm volatile("cp.async.cg.shared.global [%0], [%1], 16;" :: "r"(sa), "l"(gmem_src));
}
__device__ __forceinline__ void cp_commit() { asm volatile("cp.async.commit_group;"); }
__device__ __forceinline__ void cp_wait1()  { asm volatile("cp.async.wait_group 1;"); }
__device__ __forceinline__ void cp_wait0()  { asm volatile("cp.async.wait_group 0;"); }

// load one 16x128 chunk (k-major source: src[r][c], leading dim ld)
__device__ __forceinline__ void ldchunk(float* dst, const float* src, int ld, int tid) {
    #pragma unroll
    for (int t = 0; t < 2; t++) {
        int idx = t * 256 + tid;           // 0..511
        int r = idx >> 5;                  // 0..15
        int c4 = (idx & 31) << 2;          // 0..124
        cp16(dst + r * 128 + c4, src + r * ld + c4);
    }
}

// ---------------- 128x128 tile fp32 GEMM, f32x2 FMAs ----------------
// Computes C[m][n] = sum_k AT[k][m] * B[k][n] (+bias[n]).
// AT: k-major [K][M], pointer at column tile origin (m0). B: [K][N], at n0.
// 256 threads, 8x8 microtile, Kc=16 double-buffered via cp.async.
__device__ __forceinline__ void gemm128(
    const float* __restrict__ AT, int lda,
    const float* __restrict__ Bp, int ldb,
    float* __restrict__ Cp, int ldc,
    const float* __restrict__ biasp, int K)
{
    __shared__ float As[2][16 * 128];
    __shared__ float Bs[2][16 * 128];
    const int tid = threadIdx.x;
    const int tx = tid & 15, ty = tid >> 4;

    double acc[8][4];
    #pragma unroll
    for (int i = 0; i < 8; i++)
        #pragma unroll
        for (int j = 0; j < 4; j++) acc[i][j] = 0.0;

    const int NC = K >> 4;
    ldchunk(As[0], AT, lda, tid);
    ldchunk(Bs[0], Bp, ldb, tid);
    cp_commit();

    for (int c = 0; c < NC; ++c) {
        int cur = c & 1;
        if (c + 1 < NC) {
            int k0 = (c + 1) << 4;
            ldchunk(As[cur ^ 1], AT + k0 * lda, lda, tid);
            ldchunk(Bs[cur ^ 1], Bp + k0 * ldb, ldb, tid);
            cp_commit();
            cp_wait1();
        } else {
            cp_wait0();
        }
        __syncthreads();

        const float* Asc = As[cur];
        const float* Bsc = Bs[cur];
        #pragma unroll
        for (int k = 0; k < 16; k++) {
            float4 a0 = *(const float4*)(Asc + k * 128 + (ty << 3));
            float4 a1 = *(const float4*)(Asc + k * 128 + (ty << 3) + 4);
            double2 b0 = *(const double2*)(Bsc + k * 128 + (tx << 3));
            double2 b1 = *(const double2*)(Bsc + k * 128 + (tx << 3) + 4);
            float av[8] = {a0.x, a0.y, a0.z, a0.w, a1.x, a1.y, a1.z, a1.w};
            #pragma unroll
            for (int i = 0; i < 8; i++) {
                double ai = pack2(av[i]);
                acc[i][0] = ffma2(ai, b0.x, acc[i][0]);
                acc[i][1] = ffma2(ai, b0.y, acc[i][1]);
                acc[i][2] = ffma2(ai, b1.x, acc[i][2]);
                acc[i][3] = ffma2(ai, b1.y, acc[i][3]);
            }
        }
        __syncthreads();
    }

    float bv[8];
    #pragma unroll
    for (int j = 0; j < 8; j++) bv[j] = biasp ? biasp[(tx << 3) + j] : 0.f;

    #pragma unroll
    for (int i = 0; i < 8; i++) {
        float v[8];
        #pragma unroll
        for (int j = 0; j < 4; j++) unpack2(acc[i][j], v[2 * j], v[2 * j + 1]);
        float4 o0 = {v[0] + bv[0], v[1] + bv[1], v[2] + bv[2], v[3] + bv[3]};
        float4 o1 = {v[4] + bv[4], v[5] + bv[5], v[6] + bv[6], v[7] + bv[7]};
        float* row = Cp + ((ty << 3) + i) * ldc + (tx << 3);
        *(float4*)row = o0;
        *(float4*)(row + 4) = o1;
    }
}

// ---------------- transpose helpers ----------------
__global__ void k_transpose(const float* __restrict__ Wl, const float* __restrict__ Wtc) {
    int tid = blockIdx.x * 256 + threadIdx.x;
    if (blockIdx.y == 0) {
        if (tid < CIN * COUT) {
            int i = tid >> 8, o = tid & 255;
            d_WT[tid] = Wl[o * CIN + i];
        }
    } else {
        if (tid < COUT * COUT) {
            int o = tid >> 8, e = tid & 255;
            d_WtcT[tid] = Wtc[e * COUT + o];
        }
    }
}

// xT[b][k][m] = x[b][m][k], 32x32 smem tiles
__global__ void k_xT(const float* __restrict__ x) {
    __shared__ float tile[32][33];
    int b = blockIdx.z;
    int m0 = blockIdx.x * 32, k0 = blockIdx.y * 32;
    int tx = threadIdx.x, ty = threadIdx.y;
    #pragma unroll
    for (int i = ty; i < 32; i += 8)
        tile[i][tx] = x[b * NN * CIN + (m0 + i) * CIN + k0 + tx];
    __syncthreads();
    #pragma unroll
    for (int i = ty; i < 32; i += 8)
        d_xT[b * CIN * NN + (k0 + i) * NN + m0 + tx] = tile[tx][i];
}

// ---------------- per-batch: gate, hbias, k, v, attention, MT = (I - A)^T ----------------
__global__ __launch_bounds__(256) void k_s1(
    const float* __restrict__ ctx, const float* __restrict__ Wg,
    const float* __restrict__ bg,  const float* __restrict__ Whb,
    const float* __restrict__ Wk,  const float* __restrict__ Wv)
{
    int b = blockIdx.x;
    int tid = threadIdx.x;
    __shared__ float cs[CTXD];
    __shared__ float ks[COUT], vs[COUT], ms[COUT], invr[COUT];
    __shared__ float vmm[2];
    __shared__ float tbuf[32][257];

    for (int i = tid; i < CTXD; i += 256) cs[i] = ctx[b * CTXD + i];
    __syncthreads();

    int warp = tid >> 5, lane = tid & 31;
    for (int o = warp; o < COUT; o += 8) {
        float kk = 0.f, vv = 0.f, gg = 0.f, hb = 0.f;
        for (int c = lane; c < 256; c += 32) {
            float cv = cs[c];
            kk = fmaf(cv, Wk[o * 256 + c], kk);
            vv = fmaf(cv, Wv[o * 256 + c], vv);
        }
        for (int c = lane; c < CTXD; c += 32) {
            float cv = cs[c];
            gg = fmaf(cv, Wg[o * CTXD + c], gg);
            hb = fmaf(cv, Whb[o * CTXD + c], hb);
        }
        #pragma unroll
        for (int s = 16; s; s >>= 1) {
            kk += __shfl_xor_sync(0xffffffffu, kk, s);
            vv += __shfl_xor_sync(0xffffffffu, vv, s);
            gg += __shfl_xor_sync(0xffffffffu, gg, s);
            hb += __shfl_xor_sync(0xffffffffu, hb, s);
        }
        if (lane == 0) {
            ks[o] = kk; vs[o] = vv;
            float z = gg + bg[o];
            d_gate[b * COUT + o]  = 1.f / (1.f + expf(-z));
            d_hbias[b * COUT + o] = hb;
        }
    }
    __syncthreads();

    if (tid == 0) {
        float mx = vs[0], mn = vs[0];
        for (int i = 1; i < COUT; i++) { mx = fmaxf(mx, vs[i]); mn = fminf(mn, vs[i]); }
        vmm[0] = mx; vmm[1] = mn;
    }
    __syncthreads();

    // row-softmax prep: thread tid owns row o = tid
    {
        float kk = ks[tid];
        float m = (kk >= 0.f) ? kk * vmm[0] : kk * vmm[1];
        float r = 0.f;
        for (int e = 0; e < COUT; e++) r += expf(fmaf(kk, vs[e], -m));
        ms[tid] = m;
        invr[tid] = 1.f / r;
    }
    __syncthreads();

    // column pass: thread tid owns column e = tid of A.
    float ve = vs[tid];
    float csum = 0.f;
    for (int o = 0; o < COUT; o++)
        csum += expf(fmaf(ks[o], ve, -ms[o])) * invr[o];
    float cinv = 1.f / (1e-9f + csum);

    // write MT[e][o] = delta(e,o) - A[o][e], coalesced via smem staging
    float* MTb = d_MT + b * (COUT * COUT);
    for (int oc = 0; oc < COUT; oc += 32) {
        #pragma unroll
        for (int j = 0; j < 32; j++) {
            int o = oc + j;
            float a = expf(fmaf(ks[o], ve, -ms[o])) * invr[o] * cinv;
            tbuf[j][tid] = (o == tid ? 1.f : 0.f) - a;   // tbuf[o_local][e]
        }
        __syncthreads();
        for (int r = warp; r < COUT; r += 8)             // r = e row of MT
            MTb[r * COUT + oc + lane] = tbuf[lane][r];
        __syncthreads();
    }
}

// ---------------- GEMM wrappers ----------------
// C[b] = (I-A) @ WtcT : m=o (256), n=e' (256), k=e (256)
__global__ __launch_bounds__(256) void k_gemm_C() {
    int b = blockIdx.z;
    const float* AT = d_MT + b * (COUT * COUT) + blockIdx.x * 128;
    const float* Bp = d_WtcT + blockIdx.y * 128;
    float* Cp = d_C + b * (COUT * COUT) + blockIdx.x * 128 * COUT + blockIdx.y * 128;
    gemm128(AT, COUT, Bp, COUT, Cp, COUT, nullptr, COUT);
}

// D[b] = W_layer^T @ C[b] : m=i (128), n=e (256), k=o (256). AT = W_layer itself.
__global__ __launch_bounds__(256) void k_gemm_D(const float* __restrict__ W_layer) {
    int b = blockIdx.z;
    const float* AT = W_layer;                       // [o][i] == k-major [k][m]
    const float* Bp = d_C + b * (COUT * COUT) + blockIdx.y * 128;
    float* Cp = d_D + b * (CIN * COUT) + blockIdx.y * 128;
    gemm128(AT, CIN, Bp, COUT, Cp, COUT, nullptr, COUT);
}

// bc[b][e] = sum_o b_layer[o] * C[b][o][e] + b_tc[e]
__global__ void k_bc(const float* __restrict__ b_layer, const float* __restrict__ b_tc) {
    int b = blockIdx.x, e = threadIdx.x;
    float s = b_tc[e];
    const float* Cb = d_C + b * (COUT * COUT);
    for (int o = 0; o < COUT; o++) s = fmaf(b_layer[o], Cb[o * COUT + e], s);
    d_bc[b * COUT + e] = s;
}

// main: Y[b] = x[b] @ [WT | D[b]] + [b_layer | bc[b]]; m=n-rows (2048), n=512, k=128
__global__ __launch_bounds__(256) void k_gemm_main(const float* __restrict__ b_layer) {
    int b = blockIdx.z;
    int by = blockIdx.y;
    const float* AT = d_xT + b * (CIN * NN) + blockIdx.x * 128;   // [k=i][m=n]
    const float* Bp;
    const float* biasp;
    if (by < 2) { Bp = d_WT + by * 128;                         biasp = b_layer + by * 128; }
    else        { Bp = d_D + b * (CIN * COUT) + (by - 2) * 128; biasp = d_bc + b * COUT + (by - 2) * 128; }
    float* Cp = d_Y + b * (NN * 512) + blockIdx.x * 128 * 512 + by * 128;
    gemm128(AT, NN, Bp, COUT, Cp, 512, biasp, CIN);
}

// ---------------- BN stats over (b, e) per n ----------------
__global__ void k_bnstats() {
    int n = blockIdx.x, e = threadIdx.x;
    const float* base = d_Y + n * 512 + 256 + e;
    float s = 0.f, q = 0.f;
    #pragma unroll
    for (int b = 0; b < NB; b++) {
        float v = base[b * (NN * 512)];
        s += v; q = fmaf(v, v, q);
    }
    __shared__ float ss[256], sq[256];
    ss[e] = s; sq[e] = q;
    __syncthreads();
    for (int st = 128; st; st >>= 1) {
        if (e < st) { ss[e] += ss[e + st]; sq[e] += sq[e + st]; }
        __syncthreads();
    }
    if (e == 0) {
        float mean = ss[0] * (1.f / 8192.f);
        float var  = sq[0] * (1.f / 8192.f) - mean * mean;
        d_mean[n] = mean;
        d_rstd[n] = rsqrtf(var + 1e-5f);
    }
}

// ---------------- epilogue ----------------
__global__ void k_final(const float* __restrict__ gamma, const float* __restrict__ beta,
                        float* __restrict__ out)
{
    int idx = blockIdx.x * 256 + threadIdx.x;
    int e = idx & 255;
    int n = (idx >> 8) & (NN - 1);
    int b = idx >> 19;
    int ybase = b * (NN * 512) + n * 512;
    float x1 = d_Y[ybase + e];
    float tv = d_Y[ybase + 256 + e];
    float bn = fmaf((tv - d_mean[n]) * d_rstd[n], gamma[n], beta[n]);
    bn = fmaxf(bn, 0.f);
    out[idx] = fmaf(x1 + bn, d_gate[b * COUT + e], d_hbias[b * COUT + e]);
}

// ---------------- launch ----------------
extern "C" void kernel_launch(void* const* d_in, const int* in_sizes, int n_in,
                              void* d_out, int out_size)
{
    (void)in_sizes; (void)n_in; (void)out_size;
    const float* ctx     = (const float*)d_in[0];
    const float* x       = (const float*)d_in[1];
    const float* W_layer = (const float*)d_in[2];
    const float* b_layer = (const float*)d_in[3];
    const float* W_hbias = (const float*)d_in[4];
    const float* W_gate  = (const float*)d_in[5];
    const float* b_gate  = (const float*)d_in[6];
    const float* W_k     = (const float*)d_in[7];
    const float* W_v     = (const float*)d_in[8];
    const float* W_tc    = (const float*)d_in[9];
    const float* b_tc    = (const float*)d_in[10];
    const float* gamma   = (const float*)d_in[11];
    const float* beta    = (const float*)d_in[12];
    float* out = (float*)d_out;

    k_transpose<<<dim3(256, 2), 256>>>(W_layer, W_tc);
    k_xT<<<dim3(NN / 32, CIN / 32, NB), dim3(32, 8)>>>(x);
    k_s1<<<NB, 256>>>(ctx, W_gate, b_gate, W_hbias, W_k, W_v);
    k_gemm_C<<<dim3(2, 2, NB), 256>>>();
    k_gemm_D<<<dim3(1, 2, NB), 256>>>(W_layer);
    k_bc<<<NB, 256>>>(b_layer, b_tc);
    k_gemm_main<<<dim3(NN / 128, 4, NB), 256>>>(b_layer);
    k_bnstats<<<NN, 256>>>();
    k_final<<<(NB * NN * COUT) / 256, 256>>>(gamma, beta, out);
}

// round 5
// speedup vs baseline: 1.3156x; 1.1898x over previous
#include <cuda_runtime.h>
#include <cuda_bf16.h>
#include <math.h>

// ---------------- shapes ----------------
// B=32, N=2048, DIM_IN=128, DIM_OUT=256, DIM_CTX=259
#define NB   32
#define NN   2048
#define CIN  128
#define COUT 256
#define CTXD 259
#define MTOT (NB * NN)          // 65536 rows for main GEMM

// ---------------- device scratch ----------------
__device__ float d_gate[NB * COUT];
__device__ float d_hbias[NB * COUT];
__device__ float d_MT[NB * COUT * COUT];     // (I - A)^T [k=e][m=o]
__device__ float d_C[NB * COUT * COUT];      // (I-A) @ W_tc^T  [o][e]
__device__ float d_D[NB * CIN * COUT];       // W_layer^T @ C[b]  [i][e]
__device__ float d_WT[CIN * COUT];           // W_layer^T [i][o]
__device__ float d_WtcT[COUT * COUT];        // W_tc^T
__device__ float d_biasv[NB * 512];          // [b_layer | bc[b]]
__device__ __nv_bfloat16 d_xh[MTOT * CIN];   // x hi (bf16) [m][k]
__device__ __nv_bfloat16 d_xl[MTOT * CIN];   // x lo
__device__ __nv_bfloat16 d_Bh[NB * CIN * 512]; // B = [WT | D] hi  [b][k][n]
__device__ __nv_bfloat16 d_Bl[NB * CIN * 512]; // B lo
__device__ float d_Y[MTOT * 512];            // [x1 | t], stride 512
__device__ float d_mean[NN];
__device__ float d_rstd[NN];

// ---------------- f32x2 helpers (small GEMMs) ----------------
__device__ __forceinline__ double ffma2(double a, double b, double c) {
    double d;
    asm("fma.rn.f32x2 %0, %1, %2, %3;" : "=d"(d) : "d"(a), "d"(b), "d"(c));
    return d;
}
__device__ __forceinline__ double pack2(float x) {
    double d;
    asm("mov.b64 %0, {%1, %1};" : "=d"(d) : "f"(x));
    return d;
}
__device__ __forceinline__ void unpack2(double d, float& lo, float& hi) {
    asm("mov.b64 {%0, %1}, %2;" : "=f"(lo), "=f"(hi) : "d"(d));
}

// ---------------- cp.async helpers ----------------
__device__ __forceinline__ void cpa16(unsigned sa, const void* g) {
    asm volatile("cp.async.cg.shared.global [%0], [%1], 16;" :: "r"(sa), "l"(g));
}
__device__ __forceinline__ void cp_commit() { asm volatile("cp.async.commit_group;"); }
__device__ __forceinline__ void cp_wait1()  { asm volatile("cp.async.wait_group 1;"); }
__device__ __forceinline__ void cp_wait0()  { asm volatile("cp.async.wait_group 0;"); }

// ---------------- mma helpers ----------------
__device__ __forceinline__ void ldsm4(unsigned& r0, unsigned& r1, unsigned& r2, unsigned& r3, unsigned addr) {
    asm volatile("ldmatrix.sync.aligned.m8n8.x4.shared.b16 {%0,%1,%2,%3}, [%4];"
                 : "=r"(r0), "=r"(r1), "=r"(r2), "=r"(r3) : "r"(addr));
}
__device__ __forceinline__ void ldsm4t(unsigned& r0, unsigned& r1, unsigned& r2, unsigned& r3, unsigned addr) {
    asm volatile("ldmatrix.sync.aligned.m8n8.x4.trans.shared.b16 {%0,%1,%2,%3}, [%4];"
                 : "=r"(r0), "=r"(r1), "=r"(r2), "=r"(r3) : "r"(addr));
}
__device__ __forceinline__ void mma16816(float* c, const unsigned* a, unsigned b0, unsigned b1) {
    asm volatile("mma.sync.aligned.m16n8k16.row.col.f32.bf16.bf16.f32 "
                 "{%0,%1,%2,%3}, {%4,%5,%6,%7}, {%8,%9}, {%0,%1,%2,%3};"
                 : "+f"(c[0]), "+f"(c[1]), "+f"(c[2]), "+f"(c[3])
                 : "r"(a[0]), "r"(a[1]), "r"(a[2]), "r"(a[3]), "r"(b0), "r"(b1));
}

// ================= main GEMM: bf16 split, mma.sync =================
// Y[m][n] = sum_k x[m][k] * B[b][k][n] + bias[b][n]
// tile 128x128, BK=32, 8 warps (4m x 2n), warp tile 32x64, double buffered.
#define SA_STRIDE 40   // bf16 per A smem row (32 + 8 pad)
#define SB_STRIDE 136  // bf16 per B smem row (128 + 8 pad)
#define PERBUF 18944   // bf16 elems per buffer: 2*128*40 + 2*32*136
#define OFF_AL 5120
#define OFF_BH 10240
#define OFF_BL 14592
#define SMEM_MMA_BYTES (2 * PERBUF * 2)

__global__ __launch_bounds__(256) void k_gemm_main_mma() {
    extern __shared__ __nv_bfloat16 sm[];
    const int tid = threadIdx.x;
    const int wid = tid >> 5, lane = tid & 31;
    const int warp_m = (wid >> 1) * 32;
    const int warp_n = (wid & 1) * 64;
    const int m0 = blockIdx.x * 128;
    const int n0 = blockIdx.y * 128;
    const int b  = blockIdx.x >> 4;
    const unsigned sbase = (unsigned)__cvta_generic_to_shared(sm);

    float acc[2][8][4];
    #pragma unroll
    for (int t = 0; t < 2; t++)
        #pragma unroll
        for (int f = 0; f < 8; f++)
            #pragma unroll
            for (int r = 0; r < 4; r++) acc[t][f][r] = 0.f;

    auto fill = [&](int buf, int k0) {
        unsigned base = sbase + buf * PERBUF * 2;
        #pragma unroll
        for (int p = 0; p < 2; p++) {
            int c = p * 256 + tid;
            int ar = c >> 2, ak = (c & 3) << 3;
            cpa16(base + (ar * SA_STRIDE + ak) * 2,
                  d_xh + (size_t)(m0 + ar) * CIN + k0 + ak);
            cpa16(base + (OFF_AL + ar * SA_STRIDE + ak) * 2,
                  d_xl + (size_t)(m0 + ar) * CIN + k0 + ak);
            int br = c >> 4, bn = (c & 15) << 3;
            cpa16(base + (OFF_BH + br * SB_STRIDE + bn) * 2,
                  d_Bh + ((size_t)(b * CIN + k0 + br) << 9) + n0 + bn);
            cpa16(base + (OFF_BL + br * SB_STRIDE + bn) * 2,
                  d_Bl + ((size_t)(b * CIN + k0 + br) << 9) + n0 + bn);
        }
    };

    fill(0, 0);
    cp_commit();

    const int arow = lane & 15;            // ldmatrix row within 16
    const int asub = (lane >> 4) << 3;     // 0 or 8 (k/n sub-block)

    #pragma unroll
    for (int c = 0; c < 4; c++) {
        int cur = c & 1;
        if (c < 3) { fill(cur ^ 1, (c + 1) * 32); cp_commit(); cp_wait1(); }
        else cp_wait0();
        __syncthreads();

        unsigned base = sbase + cur * PERBUF * 2;
        #pragma unroll
        for (int ks = 0; ks < 2; ks++) {
            unsigned ah[2][4], al[2][4], bh[4][4], bl[4][4];
            #pragma unroll
            for (int t = 0; t < 2; t++) {
                int mrow = warp_m + t * 16 + arow;
                int acol = ks * 16 + asub;
                ldsm4(ah[t][0], ah[t][1], ah[t][2], ah[t][3],
                      base + (mrow * SA_STRIDE + acol) * 2);
                ldsm4(al[t][0], al[t][1], al[t][2], al[t][3],
                      base + (OFF_AL + mrow * SA_STRIDE + acol) * 2);
            }
            #pragma unroll
            for (int nb = 0; nb < 4; nb++) {
                int krow = ks * 16 + arow;
                int ncol = warp_n + nb * 16 + asub;
                ldsm4t(bh[nb][0], bh[nb][1], bh[nb][2], bh[nb][3],
                       base + (OFF_BH + krow * SB_STRIDE + ncol) * 2);
                ldsm4t(bl[nb][0], bl[nb][1], bl[nb][2], bl[nb][3],
                       base + (OFF_BL + krow * SB_STRIDE + ncol) * 2);
            }
            #pragma unroll
            for (int t = 0; t < 2; t++)
                #pragma unroll
                for (int nb = 0; nb < 4; nb++)
                    #pragma unroll
                    for (int j = 0; j < 2; j++) {
                        float* cc = acc[t][nb * 2 + j];
                        mma16816(cc, ah[t], bh[nb][2 * j], bh[nb][2 * j + 1]);
                        mma16816(cc, al[t], bh[nb][2 * j], bh[nb][2 * j + 1]);
                        mma16816(cc, ah[t], bl[nb][2 * j], bl[nb][2 * j + 1]);
                    }
        }
        __syncthreads();
    }

    // epilogue: + bias, write fp32 Y
    #pragma unroll
    for (int t = 0; t < 2; t++) {
        int row = m0 + warp_m + t * 16 + (lane >> 2);
        #pragma unroll
        for (int nb = 0; nb < 4; nb++)
            #pragma unroll
            for (int j = 0; j < 2; j++) {
                int col = n0 + warp_n + nb * 16 + j * 8 + ((lane & 3) << 1);
                float2 bv = *(const float2*)(d_biasv + b * 512 + col);
                const float* a = acc[t][nb * 2 + j];
                float2 o0 = {a[0] + bv.x, a[1] + bv.y};
                float2 o1 = {a[2] + bv.x, a[3] + bv.y};
                *(float2*)(d_Y + (size_t)row * 512 + col) = o0;
                *(float2*)(d_Y + (size_t)(row + 8) * 512 + col) = o1;
            }
    }
}

// ================= converts / packs =================
// x -> bf16 hi/lo
__global__ void k_convx(const float* __restrict__ x) {
    size_t g = (size_t)blockIdx.x * 256 + threadIdx.x;   // 4 elems each
    float4 v = *(const float4*)(x + g * 4);
    float f[4] = {v.x, v.y, v.z, v.w};
    ushort4 h, l;
    unsigned short* hp = &h.x; unsigned short* lp = &l.x;
    #pragma unroll
    for (int i = 0; i < 4; i++) {
        __nv_bfloat16 hb = __float2bfloat16(f[i]);
        __nv_bfloat16 lb = __float2bfloat16(f[i] - __bfloat162float(hb));
        hp[i] = __bfloat16_as_ushort(hb);
        lp[i] = __bfloat16_as_ushort(lb);
    }
    *(ushort4*)(d_xh + g * 4) = h;
    *(ushort4*)(d_xl + g * 4) = l;
}

// B = [WT | D] -> bf16 hi/lo, [b][k][512]
__global__ void k_packB() {
    size_t g = (size_t)blockIdx.x * 256 + threadIdx.x;   // 4 elems each
    int n = (int)(g & 127) * 4;          // 0..508
    int k = (int)(g >> 7) & 127;
    int b = (int)(g >> 14);
    const float* src = (n < 256) ? (d_WT + k * COUT + n)
                                 : (d_D + (size_t)b * CIN * COUT + k * COUT + (n - 256));
    float4 v = *(const float4*)src;
    float f[4] = {v.x, v.y, v.z, v.w};
    ushort4 h, l;
    unsigned short* hp = &h.x; unsigned short* lp = &l.x;
    #pragma unroll
    for (int i = 0; i < 4; i++) {
        __nv_bfloat16 hb = __float2bfloat16(f[i]);
        __nv_bfloat16 lb = __float2bfloat16(f[i] - __bfloat162float(hb));
        hp[i] = __bfloat16_as_ushort(hb);
        lp[i] = __bfloat16_as_ushort(lb);
    }
    size_t dst = ((size_t)(b * CIN + k) << 9) + n;
    *(ushort4*)(d_Bh + dst) = h;
    *(ushort4*)(d_Bl + dst) = l;
}

// ================= fp32 f32x2 GEMM (small per-batch GEMMs) =================
__device__ __forceinline__ void ldchunk(float* dst, const float* src, int ld, int tid) {
    #pragma unroll
    for (int t = 0; t < 2; t++) {
        int idx = t * 256 + tid;
        int r = idx >> 5;
        int c4 = (idx & 31) << 2;
        cpa16((unsigned)__cvta_generic_to_shared(dst + r * 128 + c4), src + r * ld + c4);
    }
}

__device__ __forceinline__ void gemm128(
    const float* __restrict__ AT, int lda,
    const float* __restrict__ Bp, int ldb,
    float* __restrict__ Cp, int ldc,
    const float* __restrict__ biasp, int K)
{
    __shared__ float As[2][16 * 128];
    __shared__ float Bs[2][16 * 128];
    const int tid = threadIdx.x;
    const int tx = tid & 15, ty = tid >> 4;

    double acc[8][4];
    #pragma unroll
    for (int i = 0; i < 8; i++)
        #pragma unroll
        for (int j = 0; j < 4; j++) acc[i][j] = 0.0;

    const int NC = K >> 4;
    ldchunk(As[0], AT, lda, tid);
    ldchunk(Bs[0], Bp, ldb, tid);
    cp_commit();

    for (int c = 0; c < NC; ++c) {
        int cur = c & 1;
        if (c + 1 < NC) {
            int k0 = (c + 1) << 4;
            ldchunk(As[cur ^ 1], AT + k0 * lda, lda, tid);
            ldchunk(Bs[cur ^ 1], Bp + k0 * ldb, ldb, tid);
            cp_commit();
            cp_wait1();
        } else {
            cp_wait0();
        }
        __syncthreads();

        const float* Asc = As[cur];
        const float* Bsc = Bs[cur];
        #pragma unroll 16
        for (int k = 0; k < 16; k++) {
            float4 a0 = *(const float4*)(Asc + k * 128 + (ty << 3));
            float4 a1 = *(const float4*)(Asc + k * 128 + (ty << 3) + 4);
            double2 b0 = *(const double2*)(Bsc + k * 128 + (tx << 3));
            double2 b1 = *(const double2*)(Bsc + k * 128 + (tx << 3) + 4);
            float av[8] = {a0.x, a0.y, a0.z, a0.w, a1.x, a1.y, a1.z, a1.w};
            #pragma unroll
            for (int i = 0; i < 8; i++) {
                double ai = pack2(av[i]);
                acc[i][0] = ffma2(ai, b0.x, acc[i][0]);
                acc[i][1] = ffma2(ai, b0.y, acc[i][1]);
                acc[i][2] = ffma2(ai, b1.x, acc[i][2]);
                acc[i][3] = ffma2(ai, b1.y, acc[i][3]);
            }
        }
        __syncthreads();
    }

    float bv[8];
    #pragma unroll
    for (int j = 0; j < 8; j++) bv[j] = biasp ? biasp[(tx << 3) + j] : 0.f;

    #pragma unroll
    for (int i = 0; i < 8; i++) {
        float v[8];
        #pragma unroll
        for (int j = 0; j < 4; j++) unpack2(acc[i][j], v[2 * j], v[2 * j + 1]);
        float4 o0 = {v[0] + bv[0], v[1] + bv[1], v[2] + bv[2], v[3] + bv[3]};
        float4 o1 = {v[4] + bv[4], v[5] + bv[5], v[6] + bv[6], v[7] + bv[7]};
        float* row = Cp + ((ty << 3) + i) * ldc + (tx << 3);
        *(float4*)row = o0;
        *(float4*)(row + 4) = o1;
    }
}

// ---------------- transpose helpers ----------------
__global__ void k_transpose(const float* __restrict__ Wl, const float* __restrict__ Wtc) {
    int tid = blockIdx.x * 256 + threadIdx.x;
    if (blockIdx.y == 0) {
        if (tid < CIN * COUT) {
            int i = tid >> 8, o = tid & 255;
            d_WT[tid] = Wl[o * CIN + i];
        }
    } else {
        if (tid < COUT * COUT) {
            int o = tid >> 8, e = tid & 255;
            d_WtcT[tid] = Wtc[e * COUT + o];
        }
    }
}

// ---------------- per-batch stage 1 ----------------
__global__ __launch_bounds__(256) void k_s1(
    const float* __restrict__ ctx, const float* __restrict__ Wg,
    const float* __restrict__ bg,  const float* __restrict__ Whb,
    const float* __restrict__ Wk,  const float* __restrict__ Wv)
{
    int b = blockIdx.x;
    int tid = threadIdx.x;
    __shared__ float cs[CTXD];
    __shared__ float ks[COUT], vs[COUT], ms[COUT], invr[COUT];
    __shared__ float vmm[2];
    __shared__ float tbuf[32][257];

    for (int i = tid; i < CTXD; i += 256) cs[i] = ctx[b * CTXD + i];
    __syncthreads();

    int warp = tid >> 5, lane = tid & 31;
    for (int o = warp; o < COUT; o += 8) {
        float kk = 0.f, vv = 0.f, gg = 0.f, hb = 0.f;
        for (int c = lane; c < 256; c += 32) {
            float cv = cs[c];
            kk = fmaf(cv, Wk[o * 256 + c], kk);
            vv = fmaf(cv, Wv[o * 256 + c], vv);
        }
        for (int c = lane; c < CTXD; c += 32) {
            float cv = cs[c];
            gg = fmaf(cv, Wg[o * CTXD + c], gg);
            hb = fmaf(cv, Whb[o * CTXD + c], hb);
        }
        #pragma unroll
        for (int s = 16; s; s >>= 1) {
            kk += __shfl_xor_sync(0xffffffffu, kk, s);
            vv += __shfl_xor_sync(0xffffffffu, vv, s);
            gg += __shfl_xor_sync(0xffffffffu, gg, s);
            hb += __shfl_xor_sync(0xffffffffu, hb, s);
        }
        if (lane == 0) {
            ks[o] = kk; vs[o] = vv;
            float z = gg + bg[o];
            d_gate[b * COUT + o]  = 1.f / (1.f + expf(-z));
            d_hbias[b * COUT + o] = hb;
        }
    }
    __syncthreads();

    if (tid == 0) {
        float mx = vs[0], mn = vs[0];
        for (int i = 1; i < COUT; i++) { mx = fmaxf(mx, vs[i]); mn = fminf(mn, vs[i]); }
        vmm[0] = mx; vmm[1] = mn;
    }
    __syncthreads();

    {
        float kk = ks[tid];
        float m = (kk >= 0.f) ? kk * vmm[0] : kk * vmm[1];
        float r = 0.f;
        for (int e = 0; e < COUT; e++) r += expf(fmaf(kk, vs[e], -m));
        ms[tid] = m;
        invr[tid] = 1.f / r;
    }
    __syncthreads();

    float ve = vs[tid];
    float csum = 0.f;
    for (int o = 0; o < COUT; o++)
        csum += expf(fmaf(ks[o], ve, -ms[o])) * invr[o];
    float cinv = 1.f / (1e-9f + csum);

    float* MTb = d_MT + b * (COUT * COUT);
    for (int oc = 0; oc < COUT; oc += 32) {
        #pragma unroll
        for (int j = 0; j < 32; j++) {
            int o = oc + j;
            float a = expf(fmaf(ks[o], ve, -ms[o])) * invr[o] * cinv;
            tbuf[j][tid] = (o == tid ? 1.f : 0.f) - a;
        }
        __syncthreads();
        for (int r = warp; r < COUT; r += 8)
            MTb[r * COUT + oc + lane] = tbuf[lane][r];
        __syncthreads();
    }
}

// ---------------- small GEMM wrappers ----------------
__global__ __launch_bounds__(256) void k_gemm_C() {
    int b = blockIdx.z;
    const float* AT = d_MT + b * (COUT * COUT) + blockIdx.x * 128;
    const float* Bp = d_WtcT + blockIdx.y * 128;
    float* Cp = d_C + b * (COUT * COUT) + blockIdx.x * 128 * COUT + blockIdx.y * 128;
    gemm128(AT, COUT, Bp, COUT, Cp, COUT, nullptr, COUT);
}

__global__ __launch_bounds__(256) void k_gemm_D(const float* __restrict__ W_layer) {
    int b = blockIdx.z;
    const float* AT = W_layer;
    const float* Bp = d_C + b * (COUT * COUT) + blockIdx.y * 128;
    float* Cp = d_D + b * (CIN * COUT) + blockIdx.y * 128;
    gemm128(AT, CIN, Bp, COUT, Cp, COUT, nullptr, COUT);
}

// biasv[b] = [b_layer | b_layer@C[b] + b_tc]
__global__ void k_bc(const float* __restrict__ b_layer, const float* __restrict__ b_tc) {
    int b = blockIdx.x, e = threadIdx.x;   // 512 threads
    if (e < 256) {
        d_biasv[b * 512 + e] = b_layer[e];
    } else {
        int ee = e - 256;
        float s = b_tc[ee];
        const float* Cb = d_C + b * (COUT * COUT);
        for (int o = 0; o < COUT; o++) s = fmaf(b_layer[o], Cb[o * COUT + ee], s);
        d_biasv[b * 512 + e] = s;
    }
}

// ---------------- BN stats ----------------
__global__ void k_bnstats() {
    int n = blockIdx.x, e = threadIdx.x;
    const float* base = d_Y + n * 512 + 256 + e;
    float s = 0.f, q = 0.f;
    #pragma unroll
    for (int b = 0; b < NB; b++) {
        float v = base[(size_t)b * (NN * 512)];
        s += v; q = fmaf(v, v, q);
    }
    __shared__ float ss[256], sq[256];
    ss[e] = s; sq[e] = q;
    __syncthreads();
    for (int st = 128; st; st >>= 1) {
        if (e < st) { ss[e] += ss[e + st]; sq[e] += sq[e + st]; }
        __syncthreads();
    }
    if (e == 0) {
        float mean = ss[0] * (1.f / 8192.f);
        float var  = sq[0] * (1.f / 8192.f) - mean * mean;
        d_mean[n] = mean;
        d_rstd[n] = rsqrtf(var + 1e-5f);
    }
}

// ---------------- epilogue ----------------
__global__ void k_final(const float* __restrict__ gamma, const float* __restrict__ beta,
                        float* __restrict__ out)
{
    int idx = blockIdx.x * 256 + threadIdx.x;
    int e = idx & 255;
    int n = (idx >> 8) & (NN - 1);
    int b = idx >> 19;
    size_t ybase = (size_t)b * (NN * 512) + (size_t)n * 512;
    float x1 = d_Y[ybase + e];
    float tv = d_Y[ybase + 256 + e];
    float bn = fmaf((tv - d_mean[n]) * d_rstd[n], gamma[n], beta[n]);
    bn = fmaxf(bn, 0.f);
    out[idx] = fmaf(x1 + bn, d_gate[b * COUT + e], d_hbias[b * COUT + e]);
}

// ---------------- launch ----------------
extern "C" void kernel_launch(void* const* d_in, const int* in_sizes, int n_in,
                              void* d_out, int out_size)
{
    (void)in_sizes; (void)n_in; (void)out_size;
    const float* ctx     = (const float*)d_in[0];
    const float* x       = (const float*)d_in[1];
    const float* W_layer = (const float*)d_in[2];
    const float* b_layer = (const float*)d_in[3];
    const float* W_hbias = (const float*)d_in[4];
    const float* W_gate  = (const float*)d_in[5];
    const float* b_gate  = (const float*)d_in[6];
    const float* W_k     = (const float*)d_in[7];
    const float* W_v     = (const float*)d_in[8];
    const float* W_tc    = (const float*)d_in[9];
    const float* b_tc    = (const float*)d_in[10];
    const float* gamma   = (const float*)d_in[11];
    const float* beta    = (const float*)d_in[12];
    float* out = (float*)d_out;

    static int smem_set = 0;
    if (!smem_set) {
        cudaFuncSetAttribute(k_gemm_main_mma,
                             cudaFuncAttributeMaxDynamicSharedMemorySize, SMEM_MMA_BYTES);
        smem_set = 1;
    }

    k_transpose<<<dim3(256, 2), 256>>>(W_layer, W_tc);
    k_convx<<<(MTOT * CIN) / 1024, 256>>>(x);
    k_s1<<<NB, 256>>>(ctx, W_gate, b_gate, W_hbias, W_k, W_v);
    k_gemm_C<<<dim3(2, 2, NB), 256>>>();
    k_gemm_D<<<dim3(1, 2, NB), 256>>>(W_layer);
    k_bc<<<NB, 512>>>(b_layer, b_tc);
    k_packB<<<(NB * CIN * 512) / 1024, 256>>>();
    k_gemm_main_mma<<<dim3(MTOT / 128, 4), 256, SMEM_MMA_BYTES>>>();
    k_bnstats<<<NN, 256>>>();
    k_final<<<(NB * NN * COUT) / 256, 256>>>(gamma, beta, out);
}

// round 8
// speedup vs baseline: 1.5207x; 1.1559x over previous
#include <cuda_runtime.h>
#include <cuda_fp16.h>
#include <math.h>

// ---------------- shapes ----------------
#define NB   32
#define NN   2048
#define CIN  128
#define COUT 256
#define CTXD 259
#define MTOT (NB * NN)

// ---------------- device scratch ----------------
__device__ float d_gate[NB * COUT];
__device__ float d_hbias[NB * COUT];
__device__ float d_A[NB * COUT * COUT];      // attention [o][e] per batch
__device__ float d_E[NB * COUT * CIN];       // E1^T = A^T W   [e][i]
__device__ float d_G0[CIN * COUT];           // W^T Wtc^T
__device__ float d_D[NB * CIN * COUT];       // D = G0 - E1 Wtc^T  [i][e']
__device__ float d_WT[CIN * COUT];           // W_layer^T [i][o]
__device__ float d_WtcT[COUT * COUT];        // W_tc^T
__device__ float d_biasv[NB * 512];          // [b_layer | bc]
__device__ __half d_xh[MTOT * CIN];          // x fp16 [m][k]
__device__ __half d_B0h[CIN * COUT];         // WT hi  [k][256]
__device__ __half d_B0l[CIN * COUT];         // WT lo
__device__ __half d_B1h[NB * CIN * COUT];    // D hi per batch [k][256]
__device__ __half d_B1l[NB * CIN * COUT];    // D lo
__device__ float d_Y[MTOT * 512];            // [x1 | t]
__device__ float d_ps[2 * NB * NN];          // BN partial sums
__device__ float d_pq[2 * NB * NN];          // BN partial sumsq
__device__ float d_mean[NN];
__device__ float d_rstd[NN];

// ---------------- f32x2 helpers ----------------
__device__ __forceinline__ double ffma2(double a, double b, double c) {
    double d;
    asm("fma.rn.f32x2 %0, %1, %2, %3;" : "=d"(d) : "d"(a), "d"(b), "d"(c));
    return d;
}
__device__ __forceinline__ double pack2(float x) {
    double d;
    asm("mov.b64 %0, {%1, %1};" : "=d"(d) : "f"(x));
    return d;
}
__device__ __forceinline__ void unpack2(double d, float& lo, float& hi) {
    asm("mov.b64 {%0, %1}, %2;" : "=f"(lo), "=f"(hi) : "d"(d));
}

// ---------------- cp.async helpers ----------------
__device__ __forceinline__ void cpa16(unsigned sa, const void* g) {
    asm volatile("cp.async.cg.shared.global [%0], [%1], 16;" :: "r"(sa), "l"(g));
}
__device__ __forceinline__ void cp_commit() { asm volatile("cp.async.commit_group;"); }
__device__ __forceinline__ void cp_wait1()  { asm volatile("cp.async.wait_group 1;"); }
__device__ __forceinline__ void cp_wait0()  { asm volatile("cp.async.wait_group 0;"); }

// ---------------- mma helpers ----------------
__device__ __forceinline__ void ldsm4(unsigned& r0, unsigned& r1, unsigned& r2, unsigned& r3, unsigned addr) {
    asm volatile("ldmatrix.sync.aligned.m8n8.x4.shared.b16 {%0,%1,%2,%3}, [%4];"
                 : "=r"(r0), "=r"(r1), "=r"(r2), "=r"(r3) : "r"(addr));
}
__device__ __forceinline__ void ldsm4t(unsigned& r0, unsigned& r1, unsigned& r2, unsigned& r3, unsigned addr) {
    asm volatile("ldmatrix.sync.aligned.m8n8.x4.trans.shared.b16 {%0,%1,%2,%3}, [%4];"
                 : "=r"(r0), "=r"(r1), "=r"(r2), "=r"(r3) : "r"(addr));
}
__device__ __forceinline__ void mma16816(float* c, const unsigned* a, unsigned b0, unsigned b1) {
    asm volatile("mma.sync.aligned.m16n8k16.row.col.f32.f16.f16.f32 "
                 "{%0,%1,%2,%3}, {%4,%5,%6,%7}, {%8,%9}, {%0,%1,%2,%3};"
                 : "+f"(c[0]), "+f"(c[1]), "+f"(c[2]), "+f"(c[3])
                 : "r"(a[0]), "r"(a[1]), "r"(a[2]), "r"(a[3]), "r"(b0), "r"(b1));
}

// ================= main GEMM: fp16 (x) x fp16-split (B), mma.sync =================
#define SA_STRIDE 40    // halves per A smem row (32 + 8)
#define SB_STRIDE 136   // halves per B smem row (128 + 8)
#define OFF_BH 5120
#define OFF_BL 9472
#define PERBUF 13824    // halves per buffer
#define SMEM_MMA_BYTES (2 * PERBUF * 2)

__global__ __launch_bounds__(256) void k_gemm_main_mma() {
    extern __shared__ __half sm[];
    __shared__ float2 sred[2][128];
    const int tid = threadIdx.x;
    const int wid = tid >> 5, lane = tid & 31;
    const int warp_m = (wid >> 1) * 32;
    const int warp_n = (wid & 1) * 64;
    const int mt = blockIdx.x;             // 0..511
    const int by = blockIdx.y;             // 0..3  (col tile of 512)
    const int b  = mt >> 4;
    const int m0 = mt * 128;
    const int n0 = (by & 1) * 128;         // col within 256-wide B image
    const unsigned sbase = (unsigned)__cvta_generic_to_shared(sm);

    const __half* srcBh = (by < 2) ? d_B0h : d_B1h + (size_t)b * (CIN * COUT);
    const __half* srcBl = (by < 2) ? d_B0l : d_B1l + (size_t)b * (CIN * COUT);

    float acc[2][8][4];
    #pragma unroll
    for (int t = 0; t < 2; t++)
        #pragma unroll
        for (int f = 0; f < 8; f++)
            #pragma unroll
            for (int r = 0; r < 4; r++) acc[t][f][r] = 0.f;

    auto fill = [&](int buf, int k0) {
        unsigned base = sbase + buf * (PERBUF * 2);
        #pragma unroll
        for (int p = 0; p < 2; p++) {
            int seg = p * 256 + tid;
            int r = seg >> 2, c8 = (seg & 3) << 3;
            cpa16(base + (r * SA_STRIDE + c8) * 2,
                  d_xh + (size_t)(m0 + r) * CIN + k0 + c8);
        }
        #pragma unroll
        for (int p = 0; p < 2; p++) {
            int seg = p * 256 + tid;
            int r = seg >> 4, c8 = (seg & 15) << 3;
            cpa16(base + (OFF_BH + r * SB_STRIDE + c8) * 2,
                  srcBh + (size_t)(k0 + r) * COUT + n0 + c8);
            cpa16(base + (OFF_BL + r * SB_STRIDE + c8) * 2,
                  srcBl + (size_t)(k0 + r) * COUT + n0 + c8);
        }
    };

    fill(0, 0);
    cp_commit();

    const int arow = lane & 15;
    const int asub = (lane >> 4) << 3;

    #pragma unroll
    for (int c = 0; c < 4; c++) {
        int cur = c & 1;
        if (c < 3) { fill(cur ^ 1, (c + 1) * 32); cp_commit(); cp_wait1(); }
        else cp_wait0();
        __syncthreads();

        unsigned base = sbase + cur * (PERBUF * 2);
        #pragma unroll
        for (int ks = 0; ks < 2; ks++) {
            unsigned ah[2][4], bh[4][4], bl[4][4];
            #pragma unroll
            for (int t = 0; t < 2; t++) {
                int mrow = warp_m + t * 16 + arow;
                ldsm4(ah[t][0], ah[t][1], ah[t][2], ah[t][3],
                      base + (mrow * SA_STRIDE + ks * 16 + asub) * 2);
            }
            #pragma unroll
            for (int nb = 0; nb < 4; nb++) {
                int krow = ks * 16 + arow;
                int ncol = warp_n + nb * 16 + asub;
                ldsm4t(bh[nb][0], bh[nb][1], bh[nb][2], bh[nb][3],
                       base + (OFF_BH + krow * SB_STRIDE + ncol) * 2);
                ldsm4t(bl[nb][0], bl[nb][1], bl[nb][2], bl[nb][3],
                       base + (OFF_BL + krow * SB_STRIDE + ncol) * 2);
            }
            #pragma unroll
            for (int t = 0; t < 2; t++)
                #pragma unroll
                for (int nb = 0; nb < 4; nb++)
                    #pragma unroll
                    for (int j = 0; j < 2; j++) {
                        float* cc = acc[t][nb * 2 + j];
                        mma16816(cc, ah[t], bh[nb][2 * j], bh[nb][2 * j + 1]);
                        mma16816(cc, ah[t], bl[nb][2 * j], bl[nb][2 * j + 1]);
                    }
        }
        __syncthreads();
    }

    // epilogue: + bias, write Y, accumulate BN partials (t columns only)
    float sr[2][2] = {{0.f, 0.f}, {0.f, 0.f}};
    float qr[2][2] = {{0.f, 0.f}, {0.f, 0.f}};
    #pragma unroll
    for (int t = 0; t < 2; t++) {
        size_t row = (size_t)m0 + warp_m + t * 16 + (lane >> 2);
        #pragma unroll
        for (int nb = 0; nb < 4; nb++)
            #pragma unroll
            for (int j = 0; j < 2; j++) {
                int col = by * 128 + warp_n + nb * 16 + j * 8 + ((lane & 3) << 1);
                float2 bv = *(const float2*)(d_biasv + b * 512 + col);
                const float* a = acc[t][nb * 2 + j];
                float y0 = a[0] + bv.x, y1 = a[1] + bv.y;
                float y2 = a[2] + bv.x, y3 = a[3] + bv.y;
                *(float2*)(d_Y + row * 512 + col) = make_float2(y0, y1);
                *(float2*)(d_Y + (row + 8) * 512 + col) = make_float2(y2, y3);
                sr[t][0] += y0 + y1; qr[t][0] += y0 * y0 + y1 * y1;
                sr[t][1] += y2 + y3; qr[t][1] += y2 * y2 + y3 * y3;
            }
    }
    if (by >= 2) {
        #pragma unroll
        for (int t = 0; t < 2; t++)
            #pragma unroll
            for (int rr = 0; rr < 2; rr++) {
                float s = sr[t][rr], q = qr[t][rr];
                s += __shfl_xor_sync(0xffffffffu, s, 1);
                q += __shfl_xor_sync(0xffffffffu, q, 1);
                s += __shfl_xor_sync(0xffffffffu, s, 2);
                q += __shfl_xor_sync(0xffffffffu, q, 2);
                if ((lane & 3) == 0) {
                    int r = warp_m + t * 16 + rr * 8 + (lane >> 2);
                    sred[wid & 1][r] = make_float2(s, q);
                }
            }
        __syncthreads();
        if (tid < 128) {
            float2 u = sred[0][tid], w = sred[1][tid];
            int n = (mt & 15) * 128 + tid;
            size_t o = ((size_t)(by - 2) * NB + b) * NN + n;
            d_ps[o] = u.x + w.x;
            d_pq[o] = u.y + w.y;
        }
    }
}

// ================= converts / packs =================
__global__ void k_convx(const float* __restrict__ x) {
    size_t g = (size_t)blockIdx.x * 256 + threadIdx.x;
    float4 v = *(const float4*)(x + g * 4);
    half2 p0 = __floats2half2_rn(v.x, v.y);
    half2 p1 = __floats2half2_rn(v.z, v.w);
    union { half2 h[2]; uint2 u; } cv;
    cv.h[0] = p0; cv.h[1] = p1;
    *(uint2*)(d_xh + g * 4) = cv.u;
}

__device__ __forceinline__ void split4(const float* f, uint2& h, uint2& l) {
    __half hh[4], ll[4];
    #pragma unroll
    for (int i = 0; i < 4; i++) {
        hh[i] = __float2half_rn(f[i]);
        ll[i] = __float2half_rn(f[i] - __half2float(hh[i]));
    }
    union { __half x[4]; uint2 u; } a, b2;
    #pragma unroll
    for (int i = 0; i < 4; i++) { a.x[i] = hh[i]; b2.x[i] = ll[i]; }
    h = a.u; l = b2.u;
}

__global__ void k_packB0() {
    int g = blockIdx.x * 256 + threadIdx.x;   // 8192 threads
    float4 v = *(const float4*)(d_WT + g * 4);
    float f[4] = {v.x, v.y, v.z, v.w};
    uint2 h, l;
    split4(f, h, l);
    *(uint2*)(d_B0h + g * 4) = h;
    *(uint2*)(d_B0l + g * 4) = l;
}

__global__ void k_packB1() {
    int g = blockIdx.x * 256 + threadIdx.x;   // 8192 per batch
    int b = blockIdx.y;
    float4 v = *(const float4*)(d_D + (size_t)b * (CIN * COUT) + g * 4);
    float f[4] = {v.x, v.y, v.z, v.w};
    uint2 h, l;
    split4(f, h, l);
    *(uint2*)(d_B1h + (size_t)b * (CIN * COUT) + g * 4) = h;
    *(uint2*)(d_B1l + (size_t)b * (CIN * COUT) + g * 4) = l;
}

// ================= fp32 f32x2 tile GEMM =================
__device__ __forceinline__ void ldchunk(float* dst, const float* src, int ld, int tid) {
    #pragma unroll
    for (int t = 0; t < 2; t++) {
        int idx = t * 256 + tid;
        int r = idx >> 5;
        int c4 = (idx & 31) << 2;
        cpa16((unsigned)__cvta_generic_to_shared(dst + r * 128 + c4), src + r * ld + c4);
    }
}

// out = Gp ? (Gp - acc) : (acc + colbias)
__device__ __forceinline__ void gemm128(
    const float* __restrict__ AT, int lda,
    const float* __restrict__ Bp, int ldb,
    float* __restrict__ Cp, int ldc,
    const float* __restrict__ biasp, const float* __restrict__ Gp, int K)
{
    __shared__ float As[2][16 * 128];
    __shared__ float Bs[2][16 * 128];
    const int tid = threadIdx.x;
    const int tx = tid & 15, ty = tid >> 4;

    double acc[8][4];
    #pragma unroll
    for (int i = 0; i < 8; i++)
        #pragma unroll
        for (int j = 0; j < 4; j++) acc[i][j] = 0.0;

    const int NC = K >> 4;
    ldchunk(As[0], AT, lda, tid);
    ldchunk(Bs[0], Bp, ldb, tid);
    cp_commit();

    for (int c = 0; c < NC; ++c) {
        int cur = c & 1;
        if (c + 1 < NC) {
            int k0 = (c + 1) << 4;
            ldchunk(As[cur ^ 1], AT + k0 * lda, lda, tid);
            ldchunk(Bs[cur ^ 1], Bp + k0 * ldb, ldb, tid);
            cp_commit();
            cp_wait1();
        } else {
            cp_wait0();
        }
        __syncthreads();

        const float* Asc = As[cur];
        const float* Bsc = Bs[cur];
        #pragma unroll 16
        for (int k = 0; k < 16; k++) {
            float4 a0 = *(const float4*)(Asc + k * 128 + (ty << 3));
            float4 a1 = *(const float4*)(Asc + k * 128 + (ty << 3) + 4);
            double2 b0 = *(const double2*)(Bsc + k * 128 + (tx << 3));
            double2 b1 = *(const double2*)(Bsc + k * 128 + (tx << 3) + 4);
            float av[8] = {a0.x, a0.y, a0.z, a0.w, a1.x, a1.y, a1.z, a1.w};
            #pragma unroll
            for (int i = 0; i < 8; i++) {
                double ai = pack2(av[i]);
                acc[i][0] = ffma2(ai, b0.x, acc[i][0]);
                acc[i][1] = ffma2(ai, b0.y, acc[i][1]);
                acc[i][2] = ffma2(ai, b1.x, acc[i][2]);
                acc[i][3] = ffma2(ai, b1.y, acc[i][3]);
            }
        }
        __syncthreads();
    }

    float bv[8];
    #pragma unroll
    for (int j = 0; j < 8; j++) bv[j] = biasp ? biasp[(tx << 3) + j] : 0.f;

    #pragma unroll
    for (int i = 0; i < 8; i++) {
        float v[8];
        #pragma unroll
        for (int j = 0; j < 4; j++) unpack2(acc[i][j], v[2 * j], v[2 * j + 1]);
        float* row = Cp + ((ty << 3) + i) * ldc + (tx << 3);
        if (Gp) {
            const float* gr = Gp + ((ty << 3) + i) * ldc + (tx << 3);
            float4 g0 = *(const float4*)gr;
            float4 g1 = *(const float4*)(gr + 4);
            *(float4*)row = make_float4(g0.x - v[0], g0.y - v[1], g0.z - v[2], g0.w - v[3]);
            *(float4*)(row + 4) = make_float4(g1.x - v[4], g1.y - v[5], g1.z - v[6], g1.w - v[7]);
        } else {
            *(float4*)row = make_float4(v[0] + bv[0], v[1] + bv[1], v[2] + bv[2], v[3] + bv[3]);
            *(float4*)(row + 4) = make_float4(v[4] + bv[4], v[5] + bv[5], v[6] + bv[6], v[7] + bv[7]);
        }
    }
}

// ---------------- transpose ----------------
__global__ void k_transpose(const float* __restrict__ Wl, const float* __restrict__ Wtc) {
    int tid = blockIdx.x * 256 + threadIdx.x;
    if (blockIdx.y == 0) {
        if (tid < CIN * COUT) {
            int i = tid >> 8, o = tid & 255;
            d_WT[tid] = Wl[o * CIN + i];
        }
    } else {
        if (tid < COUT * COUT) {
            int o = tid >> 8, e = tid & 255;
            d_WtcT[tid] = Wtc[e * COUT + o];
        }
    }
}

// ---------------- per-batch stage 1: gate, hbias, attention A ----------------
__global__ __launch_bounds__(256) void k_s1(
    const float* __restrict__ ctx, const float* __restrict__ Wg,
    const float* __restrict__ bg,  const float* __restrict__ Whb,
    const float* __restrict__ Wk,  const float* __restrict__ Wv)
{
    int b = blockIdx.x;
    int tid = threadIdx.x;
    __shared__ float cs[CTXD];
    __shared__ float ks[COUT], vs[COUT], ms[COUT], invr[COUT];
    __shared__ float vmm[2];

    for (int i = tid; i < CTXD; i += 256) cs[i] = ctx[b * CTXD + i];
    __syncthreads();

    int warp = tid >> 5, lane = tid & 31;
    for (int o = warp; o < COUT; o += 8) {
        float kk = 0.f, vv = 0.f, gg = 0.f, hb = 0.f;
        for (int c = lane; c < 256; c += 32) {
            float cv = cs[c];
            kk = fmaf(cv, Wk[o * 256 + c], kk);
            vv = fmaf(cv, Wv[o * 256 + c], vv);
        }
        for (int c = lane; c < CTXD; c += 32) {
            float cv = cs[c];
            gg = fmaf(cv, Wg[o * CTXD + c], gg);
            hb = fmaf(cv, Whb[o * CTXD + c], hb);
        }
        #pragma unroll
        for (int s = 16; s; s >>= 1) {
            kk += __shfl_xor_sync(0xffffffffu, kk, s);
            vv += __shfl_xor_sync(0xffffffffu, vv, s);
            gg += __shfl_xor_sync(0xffffffffu, gg, s);
            hb += __shfl_xor_sync(0xffffffffu, hb, s);
        }
        if (lane == 0) {
            ks[o] = kk; vs[o] = vv;
            float z = gg + bg[o];
            d_gate[b * COUT + o]  = 1.f / (1.f + expf(-z));
            d_hbias[b * COUT + o] = hb;
        }
    }
    __syncthreads();

    if (tid == 0) {
        float mx = vs[0], mn = vs[0];
        for (int i = 1; i < COUT; i++) { mx = fmaxf(mx, vs[i]); mn = fminf(mn, vs[i]); }
        vmm[0] = mx; vmm[1] = mn;
    }
    __syncthreads();

    {
        float kk = ks[tid];
        float m = (kk >= 0.f) ? kk * vmm[0] : kk * vmm[1];
        float r = 0.f;
        for (int e = 0; e < COUT; e++) r += expf(fmaf(kk, vs[e], -m));
        ms[tid] = m;
        invr[tid] = 1.f / r;
    }
    __syncthreads();

    // column pass: thread owns column e = tid; write A row-major (coalesced)
    float ve = vs[tid];
    float csum = 0.f;
    for (int o = 0; o < COUT; o++)
        csum += expf(fmaf(ks[o], ve, -ms[o])) * invr[o];
    float cinv = 1.f / (1e-9f + csum);

    float* Ab = d_A + b * (COUT * COUT);
    for (int o = 0; o < COUT; o++)
        Ab[o * COUT + tid] = expf(fmaf(ks[o], ve, -ms[o])) * invr[o] * cinv;
}

// ---------------- small GEMMs ----------------
// z < NB:  E1T[e][i] = sum_o A[o][e] W[o][i]       (m=e 256 -> 2 tiles, n=i 128)
// z == NB: G0[i][e'] = sum_o W[o][i] WtcT[o][e']   (m=i 128, n-tile = blockIdx.x)
__global__ __launch_bounds__(256) void k_gemm_E(const float* __restrict__ W_layer) {
    int z = blockIdx.z;
    if (z == NB) {
        gemm128(W_layer, CIN, d_WtcT + blockIdx.x * 128, COUT,
                d_G0 + blockIdx.x * 128, COUT, nullptr, nullptr, COUT);
    } else {
        const float* AT = d_A + (size_t)z * (COUT * COUT) + blockIdx.x * 128;
        float* Cp = d_E + (size_t)z * (COUT * CIN) + blockIdx.x * 128 * CIN;
        gemm128(AT, COUT, W_layer, CIN, Cp, CIN, nullptr, nullptr, COUT);
    }
}

// D[i][e'] = G0[i][e'] - sum_em E1T[em][i] WtcT[em][e']
__global__ __launch_bounds__(256) void k_gemm_D2() {
    int b = blockIdx.z;
    const float* AT = d_E + (size_t)b * (COUT * CIN);
    const float* Bp = d_WtcT + blockIdx.y * 128;
    float* Cp = d_D + (size_t)b * (CIN * COUT) + blockIdx.y * 128;
    gemm128(AT, CIN, Bp, COUT, Cp, COUT, nullptr, d_G0 + blockIdx.y * 128, COUT);
}

// biasv: [b_layer | b_tc + (b_layer^T (I-A)) Wtc^T]
__global__ void k_bc(const float* __restrict__ b_layer, const float* __restrict__ b_tc) {
    int b = blockIdx.x, e = threadIdx.x;
    __shared__ float v[COUT];
    const float* Ab = d_A + (size_t)b * (COUT * COUT);
    float s = 0.f;
    for (int o = 0; o < COUT; o++) s = fmaf(b_layer[o], Ab[o * COUT + e], s);
    v[e] = b_layer[e] - s;
    __syncthreads();
    float s2 = b_tc[e];
    for (int k = 0; k < COUT; k++) s2 = fmaf(v[k], d_WtcT[k * COUT + e], s2);
    d_biasv[b * 512 + e] = b_layer[e];
    d_biasv[b * 512 + 256 + e] = s2;
}

// ---------------- BN stats from partials ----------------
__global__ void k_bnstats2() {
    int n = blockIdx.x * 256 + threadIdx.x;
    float s = 0.f, q = 0.f;
    #pragma unroll
    for (int t = 0; t < 2 * NB; t++) {
        s += d_ps[(size_t)t * NN + n];
        q += d_pq[(size_t)t * NN + n];
    }
    float mean = s * (1.f / 8192.f);
    float var  = q * (1.f / 8192.f) - mean * mean;
    d_mean[n] = mean;
    d_rstd[n] = rsqrtf(var + 1e-5f);
}

// ---------------- epilogue ----------------
__global__ void k_final(const float* __restrict__ gamma, const float* __restrict__ beta,
                        float* __restrict__ out)
{
    int idx = blockIdx.x * 256 + threadIdx.x;
    int e = idx & 255;
    int n = (idx >> 8) & (NN - 1);
    int b = idx >> 19;
    size_t ybase = (size_t)b * (NN * 512) + (size_t)n * 512;
    float x1 = d_Y[ybase + e];
    float tv = d_Y[ybase + 256 + e];
    float bn = fmaf((tv - d_mean[n]) * d_rstd[n], gamma[n], beta[n]);
    bn = fmaxf(bn, 0.f);
    out[idx] = fmaf(x1 + bn, d_gate[b * COUT + e], d_hbias[b * COUT + e]);
}

// ---------------- launch ----------------
extern "C" void kernel_launch(void* const* d_in, const int* in_sizes, int n_in,
                              void* d_out, int out_size)
{
    (void)in_sizes; (void)n_in; (void)out_size;
    const float* ctx     = (const float*)d_in[0];
    const float* x       = (const float*)d_in[1];
    const float* W_layer = (const float*)d_in[2];
    const float* b_layer = (const float*)d_in[3];
    const float* W_hbias = (const float*)d_in[4];
    const float* W_gate  = (const float*)d_in[5];
    const float* b_gate  = (const float*)d_in[6];
    const float* W_k     = (const float*)d_in[7];
    const float* W_v     = (const float*)d_in[8];
    const float* W_tc    = (const float*)d_in[9];
    const float* b_tc    = (const float*)d_in[10];
    const float* gamma   = (const float*)d_in[11];
    const float* beta    = (const float*)d_in[12];
    float* out = (float*)d_out;

    static int smem_set = 0;
    if (!smem_set) {
        cudaFuncSetAttribute(k_gemm_main_mma,
                             cudaFuncAttributeMaxDynamicSharedMemorySize, SMEM_MMA_BYTES);
        smem_set = 1;
    }

    k_transpose<<<dim3(256, 2), 256>>>(W_layer, W_tc);
    k_convx<<<(MTOT * CIN) / 1024, 256>>>(x);
    k_s1<<<NB, 256>>>(ctx, W_gate, b_gate, W_hbias, W_k, W_v);
    k_gemm_E<<<dim3(2, 1, NB + 1), 256>>>(W_layer);
    k_gemm_D2<<<dim3(1, 2, NB), 256>>>();
    k_bc<<<NB, 256>>>(b_layer, b_tc);
    k_packB0<<<32, 256>>>();
    k_packB1<<<dim3(32, NB), 256>>>();
    k_gemm_main_mma<<<dim3(MTOT / 128, 4), 256, SMEM_MMA_BYTES>>>();
    k_bnstats2<<<NN / 256, 256>>>();
    k_final<<<(NB * NN * COUT) / 256, 256>>>(gamma, beta, out);
}

// round 12
// speedup vs baseline: 1.6573x; 1.0898x over previous
#include <cuda_runtime.h>
#include <cuda_fp16.h>
#include <math.h>

// ---------------- shapes ----------------
#define NB   32
#define NN   2048
#define CIN  128
#define COUT 256
#define CTXD 259
#define MTOT (NB * NN)

// ---------------- device scratch ----------------
__device__ float d_gate[NB * COUT];
__device__ float d_hbias[NB * COUT];
__device__ float d_A[NB * COUT * COUT];      // attention [o][e] per batch
__device__ float d_E[NB * COUT * CIN];       // E1^T = A^T W   [e][i]
__device__ float d_G0[CIN * COUT];           // W^T Wtc^T
__device__ float d_WtcT[COUT * COUT];        // W_tc^T
__device__ float d_biasv[NB * 512];          // [b_layer | bc]
__device__ __half d_xh[MTOT * CIN];          // x fp16 [m][k]
__device__ __half d_B0h[CIN * COUT];         // WT hi  [k][256]
__device__ __half d_B0l[CIN * COUT];         // WT lo
__device__ __half d_B1h[NB * CIN * COUT];    // D hi per batch [k][256]
__device__ __half d_B1l[NB * CIN * COUT];    // D lo
__device__ float d_Y[MTOT * 512];            // [x1 | t]
__device__ float d_ps[2 * NB * NN];          // BN partial sums
__device__ float d_pq[2 * NB * NN];          // BN partial sumsq
__device__ float d_mean[NN];
__device__ float d_rstd[NN];

// ---------------- f32x2 helpers ----------------
__device__ __forceinline__ double ffma2(double a, double b, double c) {
    double d;
    asm("fma.rn.f32x2 %0, %1, %2, %3;" : "=d"(d) : "d"(a), "d"(b), "d"(c));
    return d;
}
__device__ __forceinline__ double pack2(float x) {
    double d;
    asm("mov.b64 %0, {%1, %1};" : "=d"(d) : "f"(x));
    return d;
}
__device__ __forceinline__ void unpack2(double d, float& lo, float& hi) {
    asm("mov.b64 {%0, %1}, %2;" : "=f"(lo), "=f"(hi) : "d"(d));
}

// ---------------- cp.async helpers ----------------
__device__ __forceinline__ void cpa16(unsigned sa, const void* g) {
    asm volatile("cp.async.cg.shared.global [%0], [%1], 16;" :: "r"(sa), "l"(g));
}
__device__ __forceinline__ void cp_commit() { asm volatile("cp.async.commit_group;"); }
__device__ __forceinline__ void cp_wait1()  { asm volatile("cp.async.wait_group 1;"); }
__device__ __forceinline__ void cp_wait0()  { asm volatile("cp.async.wait_group 0;"); }

// ---------------- mma helpers ----------------
__device__ __forceinline__ void ldsm4(unsigned& r0, unsigned& r1, unsigned& r2, unsigned& r3, unsigned addr) {
    asm volatile("ldmatrix.sync.aligned.m8n8.x4.shared.b16 {%0,%1,%2,%3}, [%4];"
                 : "=r"(r0), "=r"(r1), "=r"(r2), "=r"(r3) : "r"(addr));
}
__device__ __forceinline__ void ldsm4t(unsigned& r0, unsigned& r1, unsigned& r2, unsigned& r3, unsigned addr) {
    asm volatile("ldmatrix.sync.aligned.m8n8.x4.trans.shared.b16 {%0,%1,%2,%3}, [%4];"
                 : "=r"(r0), "=r"(r1), "=r"(r2), "=r"(r3) : "r"(addr));
}
__device__ __forceinline__ void mma16816(float* c, const unsigned* a, unsigned b0, unsigned b1) {
    asm volatile("mma.sync.aligned.m16n8k16.row.col.f32.f16.f16.f32 "
                 "{%0,%1,%2,%3}, {%4,%5,%6,%7}, {%8,%9}, {%0,%1,%2,%3};"
                 : "+f"(c[0]), "+f"(c[1]), "+f"(c[2]), "+f"(c[3])
                 : "r"(a[0]), "r"(a[1]), "r"(a[2]), "r"(a[3]), "r"(b0), "r"(b1));
}

// ---------------- fp16 hi/lo split of 4 floats ----------------
__device__ __forceinline__ void split4(const float* f, uint2& h, uint2& l) {
    union { __half x[4]; uint2 u; } a, b2;
    #pragma unroll
    for (int i = 0; i < 4; i++) {
        __half hh = __float2half_rn(f[i]);
        a.x[i] = hh;
        b2.x[i] = __float2half_rn(f[i] - __half2float(hh));
    }
    h = a.u; l = b2.u;
}

// ================= main GEMM: fp16 (x) x fp16-split (B), full-K smem =================
#define SA 136                       // halves per smem row (128 + 8 pad)
#define OFFB1 (128 * SA)             // Bh offset (halves)
#define OFFB2 (2 * 128 * SA)         // Bl offset
#define SMEM_MMA_BYTES (3 * 128 * SA * 2)   // 104448 B

__global__ __launch_bounds__(256) void k_gemm_main_mma() {
    extern __shared__ __half sm[];
    __shared__ float2 sred[2][128];
    const int tid = threadIdx.x;
    const int wid = tid >> 5, lane = tid & 31;
    const int warp_m = (wid >> 1) * 32;
    const int warp_n = (wid & 1) * 64;
    const int mt = blockIdx.x;             // 0..511
    const int by = blockIdx.y;             // 0..3
    const int b  = mt >> 4;
    const int m0 = mt * 128;
    const int n0 = (by & 1) * 128;         // col within 256-wide B image
    const unsigned sbase = (unsigned)__cvta_generic_to_shared(sm);

    const __half* srcBh = (by < 2) ? d_B0h : d_B1h + (size_t)b * (CIN * COUT);
    const __half* srcBl = (by < 2) ? d_B0l : d_B1l + (size_t)b * (CIN * COUT);

    // one-shot load: A (x tile, full K) + Bh + Bl
    #pragma unroll
    for (int j = 0; j < 8; j++) {
        int idx = j * 256 + tid;           // 0..2047
        int r = idx >> 4, c8 = (idx & 15) << 3;
        cpa16(sbase + (r * SA + c8) * 2, d_xh + (size_t)(m0 + r) * CIN + c8);
        cpa16(sbase + (OFFB1 + r * SA + c8) * 2, srcBh + (size_t)r * COUT + n0 + c8);
        cpa16(sbase + (OFFB2 + r * SA + c8) * 2, srcBl + (size_t)r * COUT + n0 + c8);
    }
    cp_commit();

    float acc[2][8][4];
    #pragma unroll
    for (int t = 0; t < 2; t++)
        #pragma unroll
        for (int f = 0; f < 8; f++)
            #pragma unroll
            for (int r = 0; r < 4; r++) acc[t][f][r] = 0.f;

    cp_wait0();
    __syncthreads();

    const int arow = lane & 15;
    const int asub = (lane >> 4) << 3;

    #pragma unroll
    for (int ks = 0; ks < 8; ks++) {
        unsigned ah[2][4], bh[4][4], bl[4][4];
        #pragma unroll
        for (int t = 0; t < 2; t++) {
            int mrow = warp_m + t * 16 + arow;
            ldsm4(ah[t][0], ah[t][1], ah[t][2], ah[t][3],
                  sbase + (mrow * SA + ks * 16 + asub) * 2);
        }
        #pragma unroll
        for (int nb = 0; nb < 4; nb++) {
            int krow = ks * 16 + arow;
            int ncol = warp_n + nb * 16 + asub;
            ldsm4t(bh[nb][0], bh[nb][1], bh[nb][2], bh[nb][3],
                   sbase + (OFFB1 + krow * SA + ncol) * 2);
            ldsm4t(bl[nb][0], bl[nb][1], bl[nb][2], bl[nb][3],
                   sbase + (OFFB2 + krow * SA + ncol) * 2);
        }
        #pragma unroll
        for (int t = 0; t < 2; t++)
            #pragma unroll
            for (int nb = 0; nb < 4; nb++)
                #pragma unroll
                for (int j = 0; j < 2; j++) {
                    float* cc = acc[t][nb * 2 + j];
                    mma16816(cc, ah[t], bh[nb][2 * j], bh[nb][2 * j + 1]);
                    mma16816(cc, ah[t], bl[nb][2 * j], bl[nb][2 * j + 1]);
                }
    }

    // epilogue: + bias, write Y, accumulate BN partials (t columns only)
    float sr[2][2] = {{0.f, 0.f}, {0.f, 0.f}};
    float qr[2][2] = {{0.f, 0.f}, {0.f, 0.f}};
    #pragma unroll
    for (int t = 0; t < 2; t++) {
        size_t row = (size_t)m0 + warp_m + t * 16 + (lane >> 2);
        #pragma unroll
        for (int nb = 0; nb < 4; nb++)
            #pragma unroll
            for (int j = 0; j < 2; j++) {
                int col = by * 128 + warp_n + nb * 16 + j * 8 + ((lane & 3) << 1);
                float2 bv = *(const float2*)(d_biasv + b * 512 + col);
                const float* a = acc[t][nb * 2 + j];
                float y0 = a[0] + bv.x, y1 = a[1] + bv.y;
                float y2 = a[2] + bv.x, y3 = a[3] + bv.y;
                *(float2*)(d_Y + row * 512 + col) = make_float2(y0, y1);
                *(float2*)(d_Y + (row + 8) * 512 + col) = make_float2(y2, y3);
                sr[t][0] += y0 + y1; qr[t][0] += y0 * y0 + y1 * y1;
                sr[t][1] += y2 + y3; qr[t][1] += y2 * y2 + y3 * y3;
            }
    }
    if (by >= 2) {
        #pragma unroll
        for (int t = 0; t < 2; t++)
            #pragma unroll
            for (int rr = 0; rr < 2; rr++) {
                float s = sr[t][rr], q = qr[t][rr];
                s += __shfl_xor_sync(0xffffffffu, s, 1);
                q += __shfl_xor_sync(0xffffffffu, q, 1);
                s += __shfl_xor_sync(0xffffffffu, s, 2);
                q += __shfl_xor_sync(0xffffffffu, q, 2);
                if ((lane & 3) == 0) {
                    int r = warp_m + t * 16 + rr * 8 + (lane >> 2);
                    sred[wid & 1][r] = make_float2(s, q);
                }
            }
        __syncthreads();
        if (tid < 128) {
            float2 u = sred[0][tid], w = sred[1][tid];
            int n = (mt & 15) * 128 + tid;
            size_t o = ((size_t)(by - 2) * NB + b) * NN + n;
            d_ps[o] = u.x + w.x;
            d_pq[o] = u.y + w.y;
        }
    }
}

// ================= x -> fp16 =================
__global__ void k_convx(const float* __restrict__ x) {
    size_t g = (size_t)blockIdx.x * 256 + threadIdx.x;
    float4 v = *(const float4*)(x + g * 4);
    half2 p0 = __floats2half2_rn(v.x, v.y);
    half2 p1 = __floats2half2_rn(v.z, v.w);
    union { half2 h[2]; uint2 u; } cv;
    cv.h[0] = p0; cv.h[1] = p1;
    *(uint2*)(d_xh + g * 4) = cv.u;
}

// ================= 64x64 f32x2 tile GEMM (small GEMMs) =================
// C[m][n] = sum_k AT[k][m] * B[k][n]. 128 threads, micro 4x8.
// MODE 0: write fp32 C.  MODE 1: val = G - acc, split fp16 -> Hp/Lp.
template<int MODE>
__device__ __forceinline__ void gemm64(
    const float* __restrict__ AT, int lda,
    const float* __restrict__ Bp, int ldb,
    float* __restrict__ Cp, const float* __restrict__ Gp,
    __half* __restrict__ Hp, __half* __restrict__ Lp, int ldc, int K)
{
    __shared__ float As[2][16 * 64];
    __shared__ float Bs[2][16 * 64];
    const int tid = threadIdx.x;
    const int tx = tid & 7, ty = tid >> 3;   // 8 col groups x 16 row groups

    double acc[4][4];
    #pragma unroll
    for (int i = 0; i < 4; i++)
        #pragma unroll
        for (int j = 0; j < 4; j++) acc[i][j] = 0.0;

    auto ld = [&](float* dst, const float* src, int ld_) {
        #pragma unroll
        for (int t = 0; t < 2; t++) {
            int idx = t * 128 + tid;         // 0..255
            int r = idx >> 4, c4 = (idx & 15) << 2;
            cpa16((unsigned)__cvta_generic_to_shared(dst + r * 64 + c4), src + r * ld_ + c4);
        }
    };

    const int NC = K >> 4;
    ld(As[0], AT, lda);
    ld(Bs[0], Bp, ldb);
    cp_commit();

    for (int c = 0; c < NC; ++c) {
        int cur = c & 1;
        if (c + 1 < NC) {
            int k0 = (c + 1) << 4;
            ld(As[cur ^ 1], AT + k0 * lda, lda);
            ld(Bs[cur ^ 1], Bp + k0 * ldb, ldb);
            cp_commit();
            cp_wait1();
        } else {
            cp_wait0();
        }
        __syncthreads();

        const float* Asc = As[cur];
        const float* Bsc = Bs[cur];
        #pragma unroll 16
        for (int k = 0; k < 16; k++) {
            float4 a = *(const float4*)(Asc + k * 64 + (ty << 2));
            double2 b0 = *(const double2*)(Bsc + k * 64 + (tx << 3));
            double2 b1 = *(const double2*)(Bsc + k * 64 + (tx << 3) + 4);
            float av[4] = {a.x, a.y, a.z, a.w};
            #pragma unroll
            for (int i = 0; i < 4; i++) {
                double ai = pack2(av[i]);
                acc[i][0] = ffma2(ai, b0.x, acc[i][0]);
                acc[i][1] = ffma2(ai, b0.y, acc[i][1]);
                acc[i][2] = ffma2(ai, b1.x, acc[i][2]);
                acc[i][3] = ffma2(ai, b1.y, acc[i][3]);
            }
        }
        __syncthreads();
    }

    #pragma unroll
    for (int i = 0; i < 4; i++) {
        float v[8];
        #pragma unroll
        for (int j = 0; j < 4; j++) unpack2(acc[i][j], v[2 * j], v[2 * j + 1]);
        int row = (ty << 2) + i;
        int col = tx << 3;
        if (MODE == 0) {
            *(float4*)(Cp + row * ldc + col) = make_float4(v[0], v[1], v[2], v[3]);
            *(float4*)(Cp + row * ldc + col + 4) = make_float4(v[4], v[5], v[6], v[7]);
        } else {
            const float* gr = Gp + row * ldc + col;
            float4 g0 = *(const float4*)gr;
            float4 g1 = *(const float4*)(gr + 4);
            float d0[4] = {g0.x - v[0], g0.y - v[1], g0.z - v[2], g0.w - v[3]};
            float d1[4] = {g1.x - v[4], g1.y - v[5], g1.z - v[6], g1.w - v[7]};
            uint2 h0, l0, h1, l1;
            split4(d0, h0, l0);
            split4(d1, h1, l1);
            *(uint2*)(Hp + row * ldc + col) = h0;
            *(uint2*)(Hp + row * ldc + col + 4) = h1;
            *(uint2*)(Lp + row * ldc + col) = l0;
            *(uint2*)(Lp + row * ldc + col + 4) = l1;
        }
    }
}

// z < NB:  E1T[e][i] = sum_o A[o][e] W[o][i]     (m=e: 4 tiles, n=i: 2 tiles)
// z == NB: G0[i][e'] = sum_o W[o][i] WtcT[o][e'] (m=i: 2 tiles, n=e': 4 tiles)
__global__ __launch_bounds__(128) void k_gemm_E(const float* __restrict__ W_layer) {
    int z = blockIdx.z;
    if (z == NB) {
        int mt = blockIdx.x >> 2, nt = blockIdx.x & 3;
        gemm64<0>(W_layer + mt * 64, CIN, d_WtcT + nt * 64, COUT,
                  d_G0 + mt * 64 * COUT + nt * 64, nullptr, nullptr, nullptr, COUT, COUT);
    } else {
        int mt = blockIdx.x >> 1, nt = blockIdx.x & 1;
        const float* AT = d_A + (size_t)z * (COUT * COUT) + mt * 64;
        float* Cp = d_E + (size_t)z * (COUT * CIN) + mt * 64 * CIN + nt * 64;
        gemm64<0>(AT, COUT, W_layer + nt * 64, CIN, Cp, nullptr, nullptr, nullptr, CIN, COUT);
    }
}

// D[i][e'] = G0[i][e'] - sum_e E1T[e][i] WtcT[e][e']; write fp16 split to B1
__global__ __launch_bounds__(128) void k_gemm_D2() {
    int b = blockIdx.z;
    int mt = blockIdx.x >> 2, nt = blockIdx.x & 3;
    const float* AT = d_E + (size_t)b * (COUT * CIN) + mt * 64;
    __half* Hp = d_B1h + (size_t)b * (CIN * COUT) + mt * 64 * COUT + nt * 64;
    __half* Lp = d_B1l + (size_t)b * (CIN * COUT) + mt * 64 * COUT + nt * 64;
    gemm64<1>(AT, CIN, d_WtcT + nt * 64, COUT,
              nullptr, d_G0 + mt * 64 * COUT + nt * 64, Hp, Lp, COUT, COUT);
}

// ---------------- transpose + pack B0 ----------------
__global__ void k_transpose(const float* __restrict__ Wl, const float* __restrict__ Wtc) {
    int tid = blockIdx.x * 256 + threadIdx.x;           // 0..65535
    if (blockIdx.y == 0) {
        // B0 image: [k=i][o], value = W_layer[o][i], fp16 split
        if (tid < CIN * COUT) {
            int i = tid >> 8, o = tid & 255;
            float v = Wl[o * CIN + i];
            __half h = __float2half_rn(v);
            d_B0h[tid] = h;
            d_B0l[tid] = __float2half_rn(v - __half2float(h));
        }
    } else {
        if (tid < COUT * COUT) {
            int o = tid >> 8, e = tid & 255;
            d_WtcT[tid] = Wtc[e * COUT + o];
        }
    }
}

// ---------------- per-batch stage 1: gate, hbias, attention A ----------------
__global__ __launch_bounds__(256) void k_s1(
    const float* __restrict__ ctx, const float* __restrict__ Wg,
    const float* __restrict__ bg,  const float* __restrict__ Whb,
    const float* __restrict__ Wk,  const float* __restrict__ Wv)
{
    int b = blockIdx.x;
    int tid = threadIdx.x;
    __shared__ float cs[CTXD];
    __shared__ float ks[COUT], vs[COUT], ms[COUT], invr[COUT];
    __shared__ float vmm[2];

    for (int i = tid; i < CTXD; i += 256) cs[i] = ctx[b * CTXD + i];
    __syncthreads();

    int warp = tid >> 5, lane = tid & 31;
    for (int o = warp; o < COUT; o += 8) {
        float kk = 0.f, vv = 0.f, gg = 0.f, hb = 0.f;
        for (int c = lane; c < 256; c += 32) {
            float cv = cs[c];
            kk = fmaf(cv, Wk[o * 256 + c], kk);
            vv = fmaf(cv, Wv[o * 256 + c], vv);
        }
        for (int c = lane; c < CTXD; c += 32) {
            float cv = cs[c];
            gg = fmaf(cv, Wg[o * CTXD + c], gg);
            hb = fmaf(cv, Whb[o * CTXD + c], hb);
        }
        #pragma unroll
        for (int s = 16; s; s >>= 1) {
            kk += __shfl_xor_sync(0xffffffffu, kk, s);
            vv += __shfl_xor_sync(0xffffffffu, vv, s);
            gg += __shfl_xor_sync(0xffffffffu, gg, s);
            hb += __shfl_xor_sync(0xffffffffu, hb, s);
        }
        if (lane == 0) {
            ks[o] = kk; vs[o] = vv;
            float z = gg + bg[o];
            d_gate[b * COUT + o]  = 1.f / (1.f + expf(-z));
            d_hbias[b * COUT + o] = hb;
        }
    }
    __syncthreads();

    if (tid == 0) {
        float mx = vs[0], mn = vs[0];
        for (int i = 1; i < COUT; i++) { mx = fmaxf(mx, vs[i]); mn = fminf(mn, vs[i]); }
        vmm[0] = mx; vmm[1] = mn;
    }
    __syncthreads();

    {
        float kk = ks[tid];
        float m = (kk >= 0.f) ? kk * vmm[0] : kk * vmm[1];
        float r = 0.f;
        for (int e = 0; e < COUT; e++) r += expf(fmaf(kk, vs[e], -m));
        ms[tid] = m;
        invr[tid] = 1.f / r;
    }
    __syncthreads();

    float ve = vs[tid];
    float csum = 0.f;
    for (int o = 0; o < COUT; o++)
        csum += expf(fmaf(ks[o], ve, -ms[o])) * invr[o];
    float cinv = 1.f / (1e-9f + csum);

    float* Ab = d_A + b * (COUT * COUT);
    for (int o = 0; o < COUT; o++)
        Ab[o * COUT + tid] = expf(fmaf(ks[o], ve, -ms[o])) * invr[o] * cinv;
}

// biasv: [b_layer | b_tc + (b_layer^T (I-A)) Wtc^T]
__global__ void k_bc(const float* __restrict__ b_layer, const float* __restrict__ b_tc) {
    int b = blockIdx.x, e = threadIdx.x;
    __shared__ float v[COUT];
    const float* Ab = d_A + (size_t)b * (COUT * COUT);
    float s = 0.f;
    for (int o = 0; o < COUT; o++) s = fmaf(b_layer[o], Ab[o * COUT + e], s);
    v[e] = b_layer[e] - s;
    __syncthreads();
    float s2 = b_tc[e];
    for (int k = 0; k < COUT; k++) s2 = fmaf(v[k], d_WtcT[k * COUT + e], s2);
    d_biasv[b * 512 + e] = b_layer[e];
    d_biasv[b * 512 + 256 + e] = s2;
}

// ---------------- BN stats from partials ----------------
__global__ void k_bnstats2() {
    int n = blockIdx.x * 256 + threadIdx.x;
    float s = 0.f, q = 0.f;
    #pragma unroll
    for (int t = 0; t < 2 * NB; t++) {
        s += d_ps[(size_t)t * NN + n];
        q += d_pq[(size_t)t * NN + n];
    }
    float mean = s * (1.f / 8192.f);
    float var  = q * (1.f / 8192.f) - mean * mean;
    d_mean[n] = mean;
    d_rstd[n] = rsqrtf(var + 1e-5f);
}

// ---------------- epilogue (float4) ----------------
__global__ void k_final(const float* __restrict__ gamma, const float* __restrict__ beta,
                        float* __restrict__ out)
{
    int idx = blockIdx.x * 256 + threadIdx.x;    // handles 4 elems
    int e4 = (idx & 63) << 2;
    int n = (idx >> 6) & (NN - 1);
    int b = idx >> 17;
    size_t ybase = (size_t)b * (NN * 512) + (size_t)n * 512;
    float4 x1 = *(const float4*)(d_Y + ybase + e4);
    float4 tv = *(const float4*)(d_Y + ybase + 256 + e4);
    float4 gt = *(const float4*)(d_gate + b * COUT + e4);
    float4 hb = *(const float4*)(d_hbias + b * COUT + e4);
    float mr = d_mean[n], rs = d_rstd[n];
    float gm = gamma[n], bt = beta[n];
    float4 o;
    float bn;
    bn = fmaxf(fmaf((tv.x - mr) * rs, gm, bt), 0.f); o.x = fmaf(x1.x + bn, gt.x, hb.x);
    bn = fmaxf(fmaf((tv.y - mr) * rs, gm, bt), 0.f); o.y = fmaf(x1.y + bn, gt.y, hb.y);
    bn = fmaxf(fmaf((tv.z - mr) * rs, gm, bt), 0.f); o.z = fmaf(x1.z + bn, gt.z, hb.z);
    bn = fmaxf(fmaf((tv.w - mr) * rs, gm, bt), 0.f); o.w = fmaf(x1.w + bn, gt.w, hb.w);
    *(float4*)(out + (size_t)idx * 4) = o;
}

// ---------------- launch ----------------
extern "C" void kernel_launch(void* const* d_in, const int* in_sizes, int n_in,
                              void* d_out, int out_size)
{
    (void)in_sizes; (void)n_in; (void)out_size;
    const float* ctx     = (const float*)d_in[0];
    const float* x       = (const float*)d_in[1];
    const float* W_layer = (const float*)d_in[2];
    const float* b_layer = (const float*)d_in[3];
    const float* W_hbias = (const float*)d_in[4];
    const float* W_gate  = (const float*)d_in[5];
    const float* b_gate  = (const float*)d_in[6];
    const float* W_k     = (const float*)d_in[7];
    const float* W_v     = (const float*)d_in[8];
    const float* W_tc    = (const float*)d_in[9];
    const float* b_tc    = (const float*)d_in[10];
    const float* gamma   = (const float*)d_in[11];
    const float* beta    = (const float*)d_in[12];
    float* out = (float*)d_out;

    static int smem_set = 0;
    if (!smem_set) {
        cudaFuncSetAttribute(k_gemm_main_mma,
                             cudaFuncAttributeMaxDynamicSharedMemorySize, SMEM_MMA_BYTES);
        smem_set = 1;
    }

    k_transpose<<<dim3(256, 2), 256>>>(W_layer, W_tc);
    k_convx<<<(MTOT * CIN) / 1024, 256>>>(x);
    k_s1<<<NB, 256>>>(ctx, W_gate, b_gate, W_hbias, W_k, W_v);
    k_gemm_E<<<dim3(8, 1, NB + 1), 128>>>(W_layer);
    k_gemm_D2<<<dim3(8, 1, NB), 128>>>();
    k_bc<<<NB, 256>>>(b_layer, b_tc);
    k_gemm_main_mma<<<dim3(MTOT / 128, 4), 256, SMEM_MMA_BYTES>>>();
    k_bnstats2<<<NN / 256, 256>>>();
    k_final<<<(MTOT * COUT) / 1024, 256>>>(gamma, beta, out);
}

// round 13
// speedup vs baseline: 1.7810x; 1.0747x over previous
#include <cuda_runtime.h>
#include <cuda_fp16.h>
#include <math.h>

// ---------------- shapes ----------------
#define NB   32
#define NN   2048
#define CIN  128
#define COUT 256
#define CTXD 259
#define MTOT (NB * NN)

// ---------------- device scratch ----------------
__device__ float d_gate[NB * COUT];
__device__ float d_hbias[NB * COUT];
__device__ float d_A[NB * COUT * COUT];      // attention [o][e] per batch
__device__ float d_E[NB * COUT * CIN];       // E1^T = A^T W   [e][i]
__device__ float d_G0[CIN * COUT];           // W^T Wtc^T
__device__ float d_WtcT[COUT * COUT];        // W_tc^T
__device__ float d_biasv[NB * 512];          // [b_layer | bc]
__device__ __half d_xh[MTOT * CIN];          // x fp16 [m][k]
__device__ __half d_B0h[CIN * COUT];         // WT fp16 [k][256]
__device__ __half d_B1h[NB * CIN * COUT];    // D fp16 per batch [k][256]
__device__ float d_Y[MTOT * 512];            // [x1 | t]
__device__ float d_ps[2 * NB * NN];          // BN partial sums
__device__ float d_pq[2 * NB * NN];          // BN partial sumsq
__device__ float d_mean[NN];
__device__ float d_rstd[NN];

// ---------------- f32x2 helpers ----------------
__device__ __forceinline__ double ffma2(double a, double b, double c) {
    double d;
    asm("fma.rn.f32x2 %0, %1, %2, %3;" : "=d"(d) : "d"(a), "d"(b), "d"(c));
    return d;
}
__device__ __forceinline__ double fadd2(double a, double b) {
    double d;
    asm("add.rn.f32x2 %0, %1, %2;" : "=d"(d) : "d"(a), "d"(b));
    return d;
}
__device__ __forceinline__ double pack2(float x) {
    double d;
    asm("mov.b64 %0, {%1, %1};" : "=d"(d) : "f"(x));
    return d;
}
__device__ __forceinline__ void unpack2(double d, float& lo, float& hi) {
    asm("mov.b64 {%0, %1}, %2;" : "=f"(lo), "=f"(hi) : "d"(d));
}

// ---------------- cp.async helpers ----------------
__device__ __forceinline__ void cpa16(unsigned sa, const void* g) {
    asm volatile("cp.async.cg.shared.global [%0], [%1], 16;" :: "r"(sa), "l"(g));
}
__device__ __forceinline__ void cp_commit() { asm volatile("cp.async.commit_group;"); }
__device__ __forceinline__ void cp_wait1()  { asm volatile("cp.async.wait_group 1;"); }
__device__ __forceinline__ void cp_wait0()  { asm volatile("cp.async.wait_group 0;"); }

// ---------------- mma helpers ----------------
__device__ __forceinline__ void ldsm4(unsigned& r0, unsigned& r1, unsigned& r2, unsigned& r3, unsigned addr) {
    asm volatile("ldmatrix.sync.aligned.m8n8.x4.shared.b16 {%0,%1,%2,%3}, [%4];"
                 : "=r"(r0), "=r"(r1), "=r"(r2), "=r"(r3) : "r"(addr));
}
__device__ __forceinline__ void ldsm4t(unsigned& r0, unsigned& r1, unsigned& r2, unsigned& r3, unsigned addr) {
    asm volatile("ldmatrix.sync.aligned.m8n8.x4.trans.shared.b16 {%0,%1,%2,%3}, [%4];"
                 : "=r"(r0), "=r"(r1), "=r"(r2), "=r"(r3) : "r"(addr));
}
__device__ __forceinline__ void mma16816(float* c, const unsigned* a, unsigned b0, unsigned b1) {
    asm volatile("mma.sync.aligned.m16n8k16.row.col.f32.f16.f16.f32 "
                 "{%0,%1,%2,%3}, {%4,%5,%6,%7}, {%8,%9}, {%0,%1,%2,%3};"
                 : "+f"(c[0]), "+f"(c[1]), "+f"(c[2]), "+f"(c[3])
                 : "r"(a[0]), "r"(a[1]), "r"(a[2]), "r"(a[3]), "r"(b0), "r"(b1));
}

// ---------------- fp16 pack of 4 floats ----------------
__device__ __forceinline__ uint2 h4(const float* f) {
    union { __half x[4]; uint2 u; } a;
    #pragma unroll
    for (int i = 0; i < 4; i++) a.x[i] = __float2half_rn(f[i]);
    return a.u;
}

// ================= main GEMM: fp16 x fp16, full-K smem =================
#define SA 136                       // halves per smem row (128 + 8 pad)
#define OFFB1 (128 * SA)             // Bh offset (halves)
#define SMEM_MMA_BYTES (2 * 128 * SA * 2)   // 69632 B

__global__ __launch_bounds__(256) void k_gemm_main_mma() {
    extern __shared__ __half sm[];
    __shared__ float2 sred[2][128];
    const int tid = threadIdx.x;
    const int wid = tid >> 5, lane = tid & 31;
    const int warp_m = (wid >> 1) * 32;
    const int warp_n = (wid & 1) * 64;
    const int mt = blockIdx.x;             // 0..511
    const int by = blockIdx.y;             // 0..3
    const int b  = mt >> 4;
    const int m0 = mt * 128;
    const int n0 = (by & 1) * 128;         // col within 256-wide B image
    const unsigned sbase = (unsigned)__cvta_generic_to_shared(sm);

    const __half* srcBh = (by < 2) ? d_B0h : d_B1h + (size_t)b * (CIN * COUT);

    // one-shot load: A (x tile, full K) + Bh
    #pragma unroll
    for (int j = 0; j < 8; j++) {
        int idx = j * 256 + tid;           // 0..2047
        int r = idx >> 4, c8 = (idx & 15) << 3;
        cpa16(sbase + (r * SA + c8) * 2, d_xh + (size_t)(m0 + r) * CIN + c8);
        cpa16(sbase + (OFFB1 + r * SA + c8) * 2, srcBh + (size_t)r * COUT + n0 + c8);
    }
    cp_commit();

    float acc[2][8][4];
    #pragma unroll
    for (int t = 0; t < 2; t++)
        #pragma unroll
        for (int f = 0; f < 8; f++)
            #pragma unroll
            for (int r = 0; r < 4; r++) acc[t][f][r] = 0.f;

    cp_wait0();
    __syncthreads();

    const int arow = lane & 15;
    const int asub = (lane >> 4) << 3;

    #pragma unroll
    for (int ks = 0; ks < 8; ks++) {
        unsigned ah[2][4], bh[4][4];
        #pragma unroll
        for (int t = 0; t < 2; t++) {
            int mrow = warp_m + t * 16 + arow;
            ldsm4(ah[t][0], ah[t][1], ah[t][2], ah[t][3],
                  sbase + (mrow * SA + ks * 16 + asub) * 2);
        }
        #pragma unroll
        for (int nb = 0; nb < 4; nb++) {
            int krow = ks * 16 + arow;
            int ncol = warp_n + nb * 16 + asub;
            ldsm4t(bh[nb][0], bh[nb][1], bh[nb][2], bh[nb][3],
                   sbase + (OFFB1 + krow * SA + ncol) * 2);
        }
        #pragma unroll
        for (int t = 0; t < 2; t++)
            #pragma unroll
            for (int nb = 0; nb < 4; nb++)
                #pragma unroll
                for (int j = 0; j < 2; j++)
                    mma16816(acc[t][nb * 2 + j], ah[t], bh[nb][2 * j], bh[nb][2 * j + 1]);
    }

    // epilogue: + bias, write Y, accumulate BN partials (t columns only)
    float sr[2][2] = {{0.f, 0.f}, {0.f, 0.f}};
    float qr[2][2] = {{0.f, 0.f}, {0.f, 0.f}};
    #pragma unroll
    for (int t = 0; t < 2; t++) {
        size_t row = (size_t)m0 + warp_m + t * 16 + (lane >> 2);
        #pragma unroll
        for (int nb = 0; nb < 4; nb++)
            #pragma unroll
            for (int j = 0; j < 2; j++) {
                int col = by * 128 + warp_n + nb * 16 + j * 8 + ((lane & 3) << 1);
                float2 bv = *(const float2*)(d_biasv + b * 512 + col);
                const float* a = acc[t][nb * 2 + j];
                float y0 = a[0] + bv.x, y1 = a[1] + bv.y;
                float y2 = a[2] + bv.x, y3 = a[3] + bv.y;
                *(float2*)(d_Y + row * 512 + col) = make_float2(y0, y1);
                *(float2*)(d_Y + (row + 8) * 512 + col) = make_float2(y2, y3);
                sr[t][0] += y0 + y1; qr[t][0] += y0 * y0 + y1 * y1;
                sr[t][1] += y2 + y3; qr[t][1] += y2 * y2 + y3 * y3;
            }
    }
    if (by >= 2) {
        #pragma unroll
        for (int t = 0; t < 2; t++)
            #pragma unroll
            for (int rr = 0; rr < 2; rr++) {
                float s = sr[t][rr], q = qr[t][rr];
                s += __shfl_xor_sync(0xffffffffu, s, 1);
                q += __shfl_xor_sync(0xffffffffu, q, 1);
                s += __shfl_xor_sync(0xffffffffu, s, 2);
                q += __shfl_xor_sync(0xffffffffu, q, 2);
                if ((lane & 3) == 0) {
                    int r = warp_m + t * 16 + rr * 8 + (lane >> 2);
                    sred[wid & 1][r] = make_float2(s, q);
                }
            }
        __syncthreads();
        if (tid < 128) {
            float2 u = sred[0][tid], w = sred[1][tid];
            int n = (mt & 15) * 128 + tid;
            size_t o = ((size_t)(by - 2) * NB + b) * NN + n;
            d_ps[o] = u.x + w.x;
            d_pq[o] = u.y + w.y;
        }
    }
}

// ================= x -> fp16 =================
__global__ void k_convx(const float* __restrict__ x) {
    size_t g = (size_t)blockIdx.x * 256 + threadIdx.x;
    float4 v = *(const float4*)(x + g * 4);
    half2 p0 = __floats2half2_rn(v.x, v.y);
    half2 p1 = __floats2half2_rn(v.z, v.w);
    union { half2 h[2]; uint2 u; } cv;
    cv.h[0] = p0; cv.h[1] = p1;
    *(uint2*)(d_xh + g * 4) = cv.u;
}

// ================= 64x64 f32x2 tile GEMM, 256 threads, K-split x2 =================
// C[m][n] = sum_k AT[k][m] * B[k][n].  K must be 256 here.
// MODE 0: write fp32 C.  MODE 1: val = G - acc, fp16 -> Hp.
template<int MODE>
__device__ __forceinline__ void gemm64(
    const float* __restrict__ AT, int lda,
    const float* __restrict__ Bp, int ldb,
    float* __restrict__ Cp, const float* __restrict__ Gp,
    __half* __restrict__ Hp, int ldc, int K)
{
    __shared__ float As[2][2][16 * 64];   // [kg][buf]
    __shared__ float Bs[2][2][16 * 64];
    const int tid = threadIdx.x;
    const int kg = tid >> 7;              // warpgroup: k half
    const int t128 = tid & 127;
    const int tx = t128 & 7, ty = t128 >> 3;

    const int KH = K >> 1;                // 128 per kg
    const float* ATg = AT + (size_t)kg * KH * lda;
    const float* Bpg = Bp + (size_t)kg * KH * ldb;

    double acc[4][4];
    #pragma unroll
    for (int i = 0; i < 4; i++)
        #pragma unroll
        for (int j = 0; j < 4; j++) acc[i][j] = 0.0;

    auto ld = [&](float* dst, const float* src, int ld_) {
        int r = t128 >> 3, c4 = (t128 & 7) << 3;   // 16 rows x 64 cols via 128 thr x 8 floats
        cpa16((unsigned)__cvta_generic_to_shared(dst + r * 64 + c4), src + r * ld_ + c4);
        cpa16((unsigned)__cvta_generic_to_shared(dst + r * 64 + c4 + 4), src + r * ld_ + c4 + 4);
    };

    const int NC = KH >> 4;               // 8 chunks per kg
    ld(As[kg][0], ATg, lda);
    ld(Bs[kg][0], Bpg, ldb);
    cp_commit();

    for (int c = 0; c < NC; ++c) {
        int cur = c & 1;
        if (c + 1 < NC) {
            int k0 = (c + 1) << 4;
            ld(As[kg][cur ^ 1], ATg + k0 * lda, lda);
            ld(Bs[kg][cur ^ 1], Bpg + k0 * ldb, ldb);
            cp_commit();
            cp_wait1();
        } else {
            cp_wait0();
        }
        __syncthreads();

        const float* Asc = As[kg][cur];
        const float* Bsc = Bs[kg][cur];
        #pragma unroll 16
        for (int k = 0; k < 16; k++) {
            float4 a = *(const float4*)(Asc + k * 64 + (ty << 2));
            double2 b0 = *(const double2*)(Bsc + k * 64 + (tx << 3));
            double2 b1 = *(const double2*)(Bsc + k * 64 + (tx << 3) + 4);
            float av[4] = {a.x, a.y, a.z, a.w};
            #pragma unroll
            for (int i = 0; i < 4; i++) {
                double ai = pack2(av[i]);
                acc[i][0] = ffma2(ai, b0.x, acc[i][0]);
                acc[i][1] = ffma2(ai, b0.y, acc[i][1]);
                acc[i][2] = ffma2(ai, b1.x, acc[i][2]);
                acc[i][3] = ffma2(ai, b1.y, acc[i][3]);
            }
        }
        __syncthreads();
    }

    // cross-warpgroup reduction through smem (reuse As)
    double* red = (double*)&As[0][0][0];  // 2048 doubles = 16KB
    if (kg == 1) {
        #pragma unroll
        for (int i = 0; i < 4; i++)
            #pragma unroll
            for (int j = 0; j < 4; j++)
                red[t128 * 16 + i * 4 + j] = acc[i][j];
    }
    __syncthreads();
    if (kg == 0) {
        #pragma unroll
        for (int i = 0; i < 4; i++)
            #pragma unroll
            for (int j = 0; j < 4; j++)
                acc[i][j] = fadd2(acc[i][j], red[t128 * 16 + i * 4 + j]);

        #pragma unroll
        for (int i = 0; i < 4; i++) {
            float v[8];
            #pragma unroll
            for (int j = 0; j < 4; j++) unpack2(acc[i][j], v[2 * j], v[2 * j + 1]);
            int row = (ty << 2) + i;
            int col = tx << 3;
            if (MODE == 0) {
                *(float4*)(Cp + row * ldc + col) = make_float4(v[0], v[1], v[2], v[3]);
                *(float4*)(Cp + row * ldc + col + 4) = make_float4(v[4], v[5], v[6], v[7]);
            } else {
                const float* gr = Gp + row * ldc + col;
                float4 g0 = *(const float4*)gr;
                float4 g1 = *(const float4*)(gr + 4);
                float d0[4] = {g0.x - v[0], g0.y - v[1], g0.z - v[2], g0.w - v[3]};
                float d1[4] = {g1.x - v[4], g1.y - v[5], g1.z - v[6], g1.w - v[7]};
                *(uint2*)(Hp + row * ldc + col) = h4(d0);
                *(uint2*)(Hp + row * ldc + col + 4) = h4(d1);
            }
        }
    }
}

// z < NB:  E1T[e][i] = sum_o A[o][e] W[o][i]     (m=e: 4 tiles, n=i: 2 tiles)
// z == NB: G0[i][e'] = sum_o W[o][i] WtcT[o][e'] (m=i: 2 tiles, n=e': 4 tiles)
__global__ __launch_bounds__(256) void k_gemm_E(const float* __restrict__ W_layer) {
    int z = blockIdx.z;
    if (z == NB) {
        int mt = blockIdx.x >> 2, nt = blockIdx.x & 3;
        gemm64<0>(W_layer + mt * 64, CIN, d_WtcT + nt * 64, COUT,
                  d_G0 + mt * 64 * COUT + nt * 64, nullptr, nullptr, COUT, COUT);
    } else {
        int mt = blockIdx.x >> 1, nt = blockIdx.x & 1;
        const float* AT = d_A + (size_t)z * (COUT * COUT) + mt * 64;
        float* Cp = d_E + (size_t)z * (COUT * CIN) + mt * 64 * CIN + nt * 64;
        gemm64<0>(AT, COUT, W_layer + nt * 64, CIN, Cp, nullptr, nullptr, CIN, COUT);
    }
}

// D[i][e'] = G0[i][e'] - sum_e E1T[e][i] WtcT[e][e']; write fp16 to B1
__global__ __launch_bounds__(256) void k_gemm_D2() {
    int b = blockIdx.z;
    int mt = blockIdx.x >> 2, nt = blockIdx.x & 3;
    const float* AT = d_E + (size_t)b * (COUT * CIN) + mt * 64;
    __half* Hp = d_B1h + (size_t)b * (CIN * COUT) + mt * 64 * COUT + nt * 64;
    gemm64<1>(AT, CIN, d_WtcT + nt * 64, COUT,
              nullptr, d_G0 + mt * 64 * COUT + nt * 64, Hp, COUT, COUT);
}

// ---------------- transpose + pack B0 ----------------
__global__ void k_transpose(const float* __restrict__ Wl, const float* __restrict__ Wtc) {
    int tid = blockIdx.x * 256 + threadIdx.x;           // 0..65535
    if (blockIdx.y == 0) {
        if (tid < CIN * COUT) {
            int i = tid >> 8, o = tid & 255;
            d_B0h[tid] = __float2half_rn(Wl[o * CIN + i]);
        }
    } else {
        if (tid < COUT * COUT) {
            int o = tid >> 8, e = tid & 255;
            d_WtcT[tid] = Wtc[e * COUT + o];
        }
    }
}

// ---------------- per-batch stage 1: gate, hbias, attention A ----------------
__global__ __launch_bounds__(256) void k_s1(
    const float* __restrict__ ctx, const float* __restrict__ Wg,
    const float* __restrict__ bg,  const float* __restrict__ Whb,
    const float* __restrict__ Wk,  const float* __restrict__ Wv)
{
    int b = blockIdx.x;
    int tid = threadIdx.x;
    __shared__ float cs[CTXD];
    __shared__ float ks[COUT], vs[COUT], ms[COUT], invr[COUT];
    __shared__ float vmm[2];

    for (int i = tid; i < CTXD; i += 256) cs[i] = ctx[b * CTXD + i];
    __syncthreads();

    int warp = tid >> 5, lane = tid & 31;
    for (int o = warp; o < COUT; o += 8) {
        float kk = 0.f, vv = 0.f, gg = 0.f, hb = 0.f;
        for (int c = lane; c < 256; c += 32) {
            float cv = cs[c];
            kk = fmaf(cv, Wk[o * 256 + c], kk);
            vv = fmaf(cv, Wv[o * 256 + c], vv);
        }
        for (int c = lane; c < CTXD; c += 32) {
            float cv = cs[c];
            gg = fmaf(cv, Wg[o * CTXD + c], gg);
            hb = fmaf(cv, Whb[o * CTXD + c], hb);
        }
        #pragma unroll
        for (int s = 16; s; s >>= 1) {
            kk += __shfl_xor_sync(0xffffffffu, kk, s);
            vv += __shfl_xor_sync(0xffffffffu, vv, s);
            gg += __shfl_xor_sync(0xffffffffu, gg, s);
            hb += __shfl_xor_sync(0xffffffffu, hb, s);
        }
        if (lane == 0) {
            ks[o] = kk; vs[o] = vv;
            float z = gg + bg[o];
            d_gate[b * COUT + o]  = 1.f / (1.f + expf(-z));
            d_hbias[b * COUT + o] = hb;
        }
    }
    __syncthreads();

    if (tid == 0) {
        float mx = vs[0], mn = vs[0];
        for (int i = 1; i < COUT; i++) { mx = fmaxf(mx, vs[i]); mn = fminf(mn, vs[i]); }
        vmm[0] = mx; vmm[1] = mn;
    }
    __syncthreads();

    {
        float kk = ks[tid];
        float m = (kk >= 0.f) ? kk * vmm[0] : kk * vmm[1];
        float r = 0.f;
        for (int e = 0; e < COUT; e++) r += expf(fmaf(kk, vs[e], -m));
        ms[tid] = m;
        invr[tid] = 1.f / r;
    }
    __syncthreads();

    float ve = vs[tid];
    float csum = 0.f;
    for (int o = 0; o < COUT; o++)
        csum += expf(fmaf(ks[o], ve, -ms[o])) * invr[o];
    float cinv = 1.f / (1e-9f + csum);

    float* Ab = d_A + b * (COUT * COUT);
    for (int o = 0; o < COUT; o++)
        Ab[o * COUT + tid] = expf(fmaf(ks[o], ve, -ms[o])) * invr[o] * cinv;
}

// biasv: [b_layer | b_tc + (b_layer^T (I-A)) Wtc^T]
__global__ void k_bc(const float* __restrict__ b_layer, const float* __restrict__ b_tc) {
    int b = blockIdx.x, e = threadIdx.x;
    __shared__ float v[COUT];
    const float* Ab = d_A + (size_t)b * (COUT * COUT);
    float s = 0.f;
    for (int o = 0; o < COUT; o++) s = fmaf(b_layer[o], Ab[o * COUT + e], s);
    v[e] = b_layer[e] - s;
    __syncthreads();
    float s2 = b_tc[e];
    for (int k = 0; k < COUT; k++) s2 = fmaf(v[k], d_WtcT[k * COUT + e], s2);
    d_biasv[b * 512 + e] = b_layer[e];
    d_biasv[b * 512 + 256 + e] = s2;
}

// ---------------- BN stats from partials ----------------
__global__ void k_bnstats2() {
    int n = blockIdx.x * 256 + threadIdx.x;
    float s = 0.f, q = 0.f;
    #pragma unroll
    for (int t = 0; t < 2 * NB; t++) {
        s += d_ps[(size_t)t * NN + n];
        q += d_pq[(size_t)t * NN + n];
    }
    float mean = s * (1.f / 8192.f);
    float var  = q * (1.f / 8192.f) - mean * mean;
    d_mean[n] = mean;
    d_rstd[n] = rsqrtf(var + 1e-5f);
}

// ---------------- epilogue (float4) ----------------
__global__ void k_final(const float* __restrict__ gamma, const float* __restrict__ beta,
                        float* __restrict__ out)
{
    int idx = blockIdx.x * 256 + threadIdx.x;    // handles 4 elems
    int e4 = (idx & 63) << 2;
    int n = (idx >> 6) & (NN - 1);
    int b = idx >> 17;
    size_t ybase = (size_t)b * (NN * 512) + (size_t)n * 512;
    float4 x1 = *(const float4*)(d_Y + ybase + e4);
    float4 tv = *(const float4*)(d_Y + ybase + 256 + e4);
    float4 gt = *(const float4*)(d_gate + b * COUT + e4);
    float4 hb = *(const float4*)(d_hbias + b * COUT + e4);
    float mr = d_mean[n], rs = d_rstd[n];
    float gm = gamma[n], bt = beta[n];
    float4 o;
    float bn;
    bn = fmaxf(fmaf((tv.x - mr) * rs, gm, bt), 0.f); o.x = fmaf(x1.x + bn, gt.x, hb.x);
    bn = fmaxf(fmaf((tv.y - mr) * rs, gm, bt), 0.f); o.y = fmaf(x1.y + bn, gt.y, hb.y);
    bn = fmaxf(fmaf((tv.z - mr) * rs, gm, bt), 0.f); o.z = fmaf(x1.z + bn, gt.z, hb.z);
    bn = fmaxf(fmaf((tv.w - mr) * rs, gm, bt), 0.f); o.w = fmaf(x1.w + bn, gt.w, hb.w);
    *(float4*)(out + (size_t)idx * 4) = o;
}

// ---------------- launch ----------------
extern "C" void kernel_launch(void* const* d_in, const int* in_sizes, int n_in,
                              void* d_out, int out_size)
{
    (void)in_sizes; (void)n_in; (void)out_size;
    const float* ctx     = (const float*)d_in[0];
    const float* x       = (const float*)d_in[1];
    const float* W_layer = (const float*)d_in[2];
    const float* b_layer = (const float*)d_in[3];
    const float* W_hbias = (const float*)d_in[4];
    const float* W_gate  = (const float*)d_in[5];
    const float* b_gate  = (const float*)d_in[6];
    const float* W_k     = (const float*)d_in[7];
    const float* W_v     = (const float*)d_in[8];
    const float* W_tc    = (const float*)d_in[9];
    const float* b_tc    = (const float*)d_in[10];
    const float* gamma   = (const float*)d_in[11];
    const float* beta    = (const float*)d_in[12];
    float* out = (float*)d_out;

    static int smem_set = 0;
    if (!smem_set) {
        cudaFuncSetAttribute(k_gemm_main_mma,
                             cudaFuncAttributeMaxDynamicSharedMemorySize, SMEM_MMA_BYTES);
        smem_set = 1;
    }

    k_transpose<<<dim3(256, 2), 256>>>(W_layer, W_tc);
    k_convx<<<(MTOT * CIN) / 1024, 256>>>(x);
    k_s1<<<NB, 256>>>(ctx, W_gate, b_gate, W_hbias, W_k, W_v);
    k_gemm_E<<<dim3(8, 1, NB + 1), 256>>>(W_layer);
    k_gemm_D2<<<dim3(8, 1, NB), 256>>>();
    k_bc<<<NB, 256>>>(b_layer, b_tc);
    k_gemm_main_mma<<<dim3(MTOT / 128, 4), 256, SMEM_MMA_BYTES>>>();
    k_bnstats2<<<NN / 256, 256>>>();
    k_final<<<(MTOT * COUT) / 1024, 256>>>(gamma, beta, out);
}

// round 14
// speedup vs baseline: 1.8086x; 1.0155x over previous
#include <cuda_runtime.h>
#include <cuda_fp16.h>
#include <math.h>

// ---------------- shapes ----------------
#define NB   32
#define NN   2048
#define CIN  128
#define COUT 256
#define CTXD 259
#define MTOT (NB * NN)

// ---------------- device scratch ----------------
__device__ float d_gate[NB * COUT];
__device__ float d_hbias[NB * COUT];
__device__ float d_G0[CIN * COUT];           // W^T Wtc^T (fp32)
__device__ float d_WtcT[COUT * COUT];        // W_tc^T fp32 (for bc)
__device__ float d_biasv[NB * 512];          // [b_layer | bc]
__device__ __half d_xh[MTOT * CIN];          // x fp16 [m][k]
__device__ __half d_B0h[CIN * COUT];         // WT hi [i][o] (= main-GEMM B0)
__device__ __half d_WTl[CIN * COUT];         // WT lo
__device__ __half d_Wtch[COUT * COUT];       // WtcT hi [o][e]
__device__ __half d_Wtcl[COUT * COUT];       // WtcT lo
__device__ __half d_Ah[NB * COUT * COUT];    // A hi [o][e] per batch
__device__ __half d_Al[NB * COUT * COUT];    // A lo
__device__ __half d_Eth[NB * CIN * COUT];    // Et hi [i][e] per batch
__device__ __half d_Etl[NB * CIN * COUT];    // Et lo
__device__ __half d_B1h[NB * CIN * COUT];    // D fp16 per batch [i][e']
__device__ float d_Y[MTOT * 512];            // [x1 | t]
__device__ float d_ps[2 * NB * NN];          // BN partial sums
__device__ float d_pq[2 * NB * NN];          // BN partial sumsq
__device__ float d_mean[NN];
__device__ float d_rstd[NN];

// ---------------- cp.async helpers ----------------
__device__ __forceinline__ void cpa16(unsigned sa, const void* g) {
    asm volatile("cp.async.cg.shared.global [%0], [%1], 16;" :: "r"(sa), "l"(g));
}
__device__ __forceinline__ void cp_commit() { asm volatile("cp.async.commit_group;"); }
__device__ __forceinline__ void cp_wait1()  { asm volatile("cp.async.wait_group 1;"); }
__device__ __forceinline__ void cp_wait0()  { asm volatile("cp.async.wait_group 0;"); }

// ---------------- mma helpers ----------------
__device__ __forceinline__ void ldsm4(unsigned& r0, unsigned& r1, unsigned& r2, unsigned& r3, unsigned addr) {
    asm volatile("ldmatrix.sync.aligned.m8n8.x4.shared.b16 {%0,%1,%2,%3}, [%4];"
                 : "=r"(r0), "=r"(r1), "=r"(r2), "=r"(r3) : "r"(addr));
}
__device__ __forceinline__ void ldsm4t(unsigned& r0, unsigned& r1, unsigned& r2, unsigned& r3, unsigned addr) {
    asm volatile("ldmatrix.sync.aligned.m8n8.x4.trans.shared.b16 {%0,%1,%2,%3}, [%4];"
                 : "=r"(r0), "=r"(r1), "=r"(r2), "=r"(r3) : "r"(addr));
}
__device__ __forceinline__ void mma16816(float* c, const unsigned* a, unsigned b0, unsigned b1) {
    asm volatile("mma.sync.aligned.m16n8k16.row.col.f32.f16.f16.f32 "
                 "{%0,%1,%2,%3}, {%4,%5,%6,%7}, {%8,%9}, {%0,%1,%2,%3};"
                 : "+f"(c[0]), "+f"(c[1]), "+f"(c[2]), "+f"(c[3])
                 : "r"(a[0]), "r"(a[1]), "r"(a[2]), "r"(a[3]), "r"(b0), "r"(b1));
}

// ================= main GEMM: fp16 x fp16, full-K smem =================
#define SA 136                       // halves per smem row (128 + 8 pad)
#define OFFB1 (128 * SA)             // Bh offset (halves)
#define SMEM_MMA_BYTES (2 * 128 * SA * 2)   // 69632 B

__global__ __launch_bounds__(256) void k_gemm_main_mma() {
    extern __shared__ __half sm[];
    __shared__ float2 sred[2][128];
    const int tid = threadIdx.x;
    const int wid = tid >> 5, lane = tid & 31;
    const int warp_m = (wid >> 1) * 32;
    const int warp_n = (wid & 1) * 64;
    const int mt = blockIdx.x;             // 0..511
    const int by = blockIdx.y;             // 0..3
    const int b  = mt >> 4;
    const int m0 = mt * 128;
    const int n0 = (by & 1) * 128;         // col within 256-wide B image
    const unsigned sbase = (unsigned)__cvta_generic_to_shared(sm);

    const __half* srcBh = (by < 2) ? d_B0h : d_B1h + (size_t)b * (CIN * COUT);

    // one-shot load: A (x tile, full K) + Bh
    #pragma unroll
    for (int j = 0; j < 8; j++) {
        int idx = j * 256 + tid;           // 0..2047
        int r = idx >> 4, c8 = (idx & 15) << 3;
        cpa16(sbase + (r * SA + c8) * 2, d_xh + (size_t)(m0 + r) * CIN + c8);
        cpa16(sbase + (OFFB1 + r * SA + c8) * 2, srcBh + (size_t)r * COUT + n0 + c8);
    }
    cp_commit();

    float acc[2][8][4];
    #pragma unroll
    for (int t = 0; t < 2; t++)
        #pragma unroll
        for (int f = 0; f < 8; f++)
            #pragma unroll
            for (int r = 0; r < 4; r++) acc[t][f][r] = 0.f;

    cp_wait0();
    __syncthreads();

    const int arow = lane & 15;
    const int asub = (lane >> 4) << 3;

    #pragma unroll
    for (int ks = 0; ks < 8; ks++) {
        unsigned ah[2][4], bh[4][4];
        #pragma unroll
        for (int t = 0; t < 2; t++) {
            int mrow = warp_m + t * 16 + arow;
            ldsm4(ah[t][0], ah[t][1], ah[t][2], ah[t][3],
                  sbase + (mrow * SA + ks * 16 + asub) * 2);
        }
        #pragma unroll
        for (int nb = 0; nb < 4; nb++) {
            int krow = ks * 16 + arow;
            int ncol = warp_n + nb * 16 + asub;
            ldsm4t(bh[nb][0], bh[nb][1], bh[nb][2], bh[nb][3],
                   sbase + (OFFB1 + krow * SA + ncol) * 2);
        }
        #pragma unroll
        for (int t = 0; t < 2; t++)
            #pragma unroll
            for (int nb = 0; nb < 4; nb++)
                #pragma unroll
                for (int j = 0; j < 2; j++)
                    mma16816(acc[t][nb * 2 + j], ah[t], bh[nb][2 * j], bh[nb][2 * j + 1]);
    }

    // epilogue: + bias, write Y, accumulate BN partials (t columns only)
    float sr[2][2] = {{0.f, 0.f}, {0.f, 0.f}};
    float qr[2][2] = {{0.f, 0.f}, {0.f, 0.f}};
    #pragma unroll
    for (int t = 0; t < 2; t++) {
        size_t row = (size_t)m0 + warp_m + t * 16 + (lane >> 2);
        #pragma unroll
        for (int nb = 0; nb < 4; nb++)
            #pragma unroll
            for (int j = 0; j < 2; j++) {
                int col = by * 128 + warp_n + nb * 16 + j * 8 + ((lane & 3) << 1);
                float2 bv = *(const float2*)(d_biasv + b * 512 + col);
                const float* a = acc[t][nb * 2 + j];
                float y0 = a[0] + bv.x, y1 = a[1] + bv.y;
                float y2 = a[2] + bv.x, y3 = a[3] + bv.y;
                *(float2*)(d_Y + row * 512 + col) = make_float2(y0, y1);
                *(float2*)(d_Y + (row + 8) * 512 + col) = make_float2(y2, y3);
                sr[t][0] += y0 + y1; qr[t][0] += y0 * y0 + y1 * y1;
                sr[t][1] += y2 + y3; qr[t][1] += y2 * y2 + y3 * y3;
            }
    }
    if (by >= 2) {
        #pragma unroll
        for (int t = 0; t < 2; t++)
            #pragma unroll
            for (int rr = 0; rr < 2; rr++) {
                float s = sr[t][rr], q = qr[t][rr];
                s += __shfl_xor_sync(0xffffffffu, s, 1);
                q += __shfl_xor_sync(0xffffffffu, q, 1);
                s += __shfl_xor_sync(0xffffffffu, s, 2);
                q += __shfl_xor_sync(0xffffffffu, q, 2);
                if ((lane & 3) == 0) {
                    int r = warp_m + t * 16 + rr * 8 + (lane >> 2);
                    sred[wid & 1][r] = make_float2(s, q);
                }
            }
        __syncthreads();
        if (tid < 128) {
            float2 u = sred[0][tid], w = sred[1][tid];
            int n = (mt & 15) * 128 + tid;
            size_t o = ((size_t)(by - 2) * NB + b) * NN + n;
            d_ps[o] = u.x + w.x;
            d_pq[o] = u.y + w.y;
        }
    }
}

// ================= small tensor GEMM: 128x128 tile, K=256, 3-MMA hi/lo split =================
// A: [128][256] row-major fp16 pair (Agh/Agl, lda). B: [256][128+] row-major pair (ldb).
// MODE 0: Cf = acc (fp32). MODE 1: split acc -> Ch/Cl fp16. MODE 2: v = G - acc -> Ch fp16.
#define TSA 40                         // A chunk stride (32 k + 8 pad), halves
#define TS_AH 0
#define TS_AL (128 * TSA)              // 5120
#define TS_BH (2 * 128 * TSA)          // 10240
#define TS_BL (TS_BH + 32 * SA)        // + 32*136 = 14592
#define TS_PER (TS_BL + 32 * SA)       // 18944 halves / buffer
#define SMEM_TS_BYTES (2 * TS_PER * 2) // 75776 B

template<int MODE>
__device__ __forceinline__ void tcg128(
    const __half* __restrict__ Agh, const __half* __restrict__ Agl, int lda,
    const __half* __restrict__ Bgh, const __half* __restrict__ Bgl, int ldb,
    float* __restrict__ Cf, const float* __restrict__ G,
    __half* __restrict__ Ch, __half* __restrict__ Cl, int ldc)
{
    extern __shared__ __half sm[];
    const int tid = threadIdx.x;
    const int wid = tid >> 5, lane = tid & 31;
    const int warp_m = (wid >> 1) * 32;
    const int warp_n = (wid & 1) * 64;
    const unsigned sbase = (unsigned)__cvta_generic_to_shared(sm);

    auto fill = [&](int buf, int k0) {
        unsigned base = sbase + buf * (TS_PER * 2);
        #pragma unroll
        for (int j = 0; j < 2; j++) {
            int idx = j * 256 + tid;               // 0..511
            int r = idx >> 2, c8 = (idx & 3) << 3; // A: 128 rows x 32k
            cpa16(base + (TS_AH + r * TSA + c8) * 2, Agh + (size_t)r * lda + k0 + c8);
            cpa16(base + (TS_AL + r * TSA + c8) * 2, Agl + (size_t)r * lda + k0 + c8);
            int br = idx >> 4, bc8 = (idx & 15) << 3; // B: 32 rows x 128n
            cpa16(base + (TS_BH + br * SA + bc8) * 2, Bgh + (size_t)(k0 + br) * ldb + bc8);
            cpa16(base + (TS_BL + br * SA + bc8) * 2, Bgl + (size_t)(k0 + br) * ldb + bc8);
        }
    };

    float acc[2][8][4];
    #pragma unroll
    for (int t = 0; t < 2; t++)
        #pragma unroll
        for (int f = 0; f < 8; f++)
            #pragma unroll
            for (int r = 0; r < 4; r++) acc[t][f][r] = 0.f;

    fill(0, 0);
    cp_commit();

    const int arow = lane & 15;
    const int asub = (lane >> 4) << 3;

    #pragma unroll
    for (int c = 0; c < 8; c++) {
        int cur = c & 1;
        if (c < 7) { fill(cur ^ 1, (c + 1) * 32); cp_commit(); cp_wait1(); }
        else cp_wait0();
        __syncthreads();

        unsigned base = sbase + cur * (TS_PER * 2);
        #pragma unroll
        for (int ks = 0; ks < 2; ks++) {
            unsigned ah[2][4], al[2][4], bh[4][4], bl[4][4];
            #pragma unroll
            for (int t = 0; t < 2; t++) {
                int mrow = warp_m + t * 16 + arow;
                int acol = ks * 16 + asub;
                ldsm4(ah[t][0], ah[t][1], ah[t][2], ah[t][3],
                      base + (TS_AH + mrow * TSA + acol) * 2);
                ldsm4(al[t][0], al[t][1], al[t][2], al[t][3],
                      base + (TS_AL + mrow * TSA + acol) * 2);
            }
            #pragma unroll
            for (int nb = 0; nb < 4; nb++) {
                int krow = ks * 16 + arow;
                int ncol = warp_n + nb * 16 + asub;
                ldsm4t(bh[nb][0], bh[nb][1], bh[nb][2], bh[nb][3],
                       base + (TS_BH + krow * SA + ncol) * 2);
                ldsm4t(bl[nb][0], bl[nb][1], bl[nb][2], bl[nb][3],
                       base + (TS_BL + krow * SA + ncol) * 2);
            }
            #pragma unroll
            for (int t = 0; t < 2; t++)
                #pragma unroll
                for (int nb = 0; nb < 4; nb++)
                    #pragma unroll
                    for (int j = 0; j < 2; j++) {
                        float* cc = acc[t][nb * 2 + j];
                        mma16816(cc, ah[t], bh[nb][2 * j], bh[nb][2 * j + 1]);
                        mma16816(cc, al[t], bh[nb][2 * j], bh[nb][2 * j + 1]);
                        mma16816(cc, ah[t], bl[nb][2 * j], bl[nb][2 * j + 1]);
                    }
        }
        __syncthreads();
    }

    // epilogue
    #pragma unroll
    for (int t = 0; t < 2; t++) {
        int row = warp_m + t * 16 + (lane >> 2);
        #pragma unroll
        for (int nb = 0; nb < 4; nb++)
            #pragma unroll
            for (int j = 0; j < 2; j++) {
                int col = warp_n + nb * 16 + j * 8 + ((lane & 3) << 1);
                const float* a = acc[t][nb * 2 + j];
                #pragma unroll
                for (int rr = 0; rr < 2; rr++) {
                    int r = row + rr * 8;
                    float v0 = a[2 * rr], v1 = a[2 * rr + 1];
                    if (MODE == 0) {
                        *(float2*)(Cf + (size_t)r * ldc + col) = make_float2(v0, v1);
                    } else if (MODE == 1) {
                        __half h0 = __float2half_rn(v0), h1 = __float2half_rn(v1);
                        union { __half h[2]; unsigned u; } ph, pl;
                        ph.h[0] = h0; ph.h[1] = h1;
                        pl.h[0] = __float2half_rn(v0 - __half2float(h0));
                        pl.h[1] = __float2half_rn(v1 - __half2float(h1));
                        *(unsigned*)(Ch + (size_t)r * ldc + col) = ph.u;
                        *(unsigned*)(Cl + (size_t)r * ldc + col) = pl.u;
                    } else {
                        float2 g = *(const float2*)(G + (size_t)r * ldc + col);
                        union { __half h[2]; unsigned u; } ph;
                        ph.h[0] = __float2half_rn(g.x - v0);
                        ph.h[1] = __float2half_rn(g.y - v1);
                        *(unsigned*)(Ch + (size_t)r * ldc + col) = ph.u;
                    }
                }
            }
    }
}

// z < NB:  Et[i][e] = sum_o W[o][i]*A[o][e]  (fp16 pair out), n-tile = blockIdx.x
// z == NB: G0[i][e'] = sum_o W[o][i]*WtcT[o][e']  (fp32 out)
__global__ __launch_bounds__(256) void k_gemm_Et() {
    int z = blockIdx.z, nt = blockIdx.x;
    if (z == NB) {
        tcg128<0>(d_B0h, d_WTl, COUT, d_Wtch + nt * 128, d_Wtcl + nt * 128, COUT,
                  d_G0 + nt * 128, nullptr, nullptr, nullptr, COUT);
    } else {
        const __half* Bh = d_Ah + (size_t)z * (COUT * COUT) + nt * 128;
        const __half* Bl = d_Al + (size_t)z * (COUT * COUT) + nt * 128;
        tcg128<1>(d_B0h, d_WTl, COUT, Bh, Bl, COUT,
                  nullptr, nullptr,
                  d_Eth + (size_t)z * (CIN * COUT) + nt * 128,
                  d_Etl + (size_t)z * (CIN * COUT) + nt * 128, COUT);
    }
}

// D[i][e'] = G0[i][e'] - sum_e Et[i][e]*WtcT[e][e']  -> fp16 B1h
__global__ __launch_bounds__(256) void k_gemm_D2() {
    int b = blockIdx.z, nt = blockIdx.x;
    tcg128<2>(d_Eth + (size_t)b * (CIN * COUT), d_Etl + (size_t)b * (CIN * COUT), COUT,
              d_Wtch + nt * 128, d_Wtcl + nt * 128, COUT,
              nullptr, d_G0 + nt * 128,
              d_B1h + (size_t)b * (CIN * COUT) + nt * 128, nullptr, COUT);
}

// ================= x -> fp16 =================
__global__ void k_convx(const float* __restrict__ x) {
    size_t g = (size_t)blockIdx.x * 256 + threadIdx.x;
    float4 v = *(const float4*)(x + g * 4);
    half2 p0 = __floats2half2_rn(v.x, v.y);
    half2 p1 = __floats2half2_rn(v.z, v.w);
    union { half2 h[2]; uint2 u; } cv;
    cv.h[0] = p0; cv.h[1] = p1;
    *(uint2*)(d_xh + g * 4) = cv.u;
}

// ---------------- transpose + fp16 weight images ----------------
__global__ void k_transpose(const float* __restrict__ Wl, const float* __restrict__ Wtc) {
    int tid = blockIdx.x * 256 + threadIdx.x;           // 0..65535
    if (blockIdx.y == 0) {
        if (tid < CIN * COUT) {
            int i = tid >> 8, o = tid & 255;
            float v = Wl[o * CIN + i];
            __half h = __float2half_rn(v);
            d_B0h[tid] = h;
            d_WTl[tid] = __float2half_rn(v - __half2float(h));
        }
    } else {
        if (tid < COUT * COUT) {
            int o = tid >> 8, e = tid & 255;
            float v = Wtc[e * COUT + o];
            d_WtcT[tid] = v;
            __half h = __float2half_rn(v);
            d_Wtch[tid] = h;
            d_Wtcl[tid] = __float2half_rn(v - __half2float(h));
        }
    }
}

// ---------------- per-batch stage 1: gate, hbias, attention A (fp16 split) ----------------
__global__ __launch_bounds__(256) void k_s1(
    const float* __restrict__ ctx, const float* __restrict__ Wg,
    const float* __restrict__ bg,  const float* __restrict__ Whb,
    const float* __restrict__ Wk,  const float* __restrict__ Wv)
{
    int b = blockIdx.x;
    int tid = threadIdx.x;
    __shared__ float cs[CTXD];
    __shared__ float ks[COUT], vs[COUT], ms[COUT], invr[COUT];
    __shared__ float vmm[2];

    for (int i = tid; i < CTXD; i += 256) cs[i] = ctx[b * CTXD + i];
    __syncthreads();

    int warp = tid >> 5, lane = tid & 31;
    for (int o = warp; o < COUT; o += 8) {
        float kk = 0.f, vv = 0.f, gg = 0.f, hb = 0.f;
        for (int c = lane; c < 256; c += 32) {
            float cv = cs[c];
            kk = fmaf(cv, Wk[o * 256 + c], kk);
            vv = fmaf(cv, Wv[o * 256 + c], vv);
        }
        for (int c = lane; c < CTXD; c += 32) {
            float cv = cs[c];
            gg = fmaf(cv, Wg[o * CTXD + c], gg);
            hb = fmaf(cv, Whb[o * CTXD + c], hb);
        }
        #pragma unroll
        for (int s = 16; s; s >>= 1) {
            kk += __shfl_xor_sync(0xffffffffu, kk, s);
            vv += __shfl_xor_sync(0xffffffffu, vv, s);
            gg += __shfl_xor_sync(0xffffffffu, gg, s);
            hb += __shfl_xor_sync(0xffffffffu, hb, s);
        }
        if (lane == 0) {
            ks[o] = kk; vs[o] = vv;
            float z = gg + bg[o];
            d_gate[b * COUT + o]  = 1.f / (1.f + expf(-z));
            d_hbias[b * COUT + o] = hb;
        }
    }
    __syncthreads();

    if (tid == 0) {
        float mx = vs[0], mn = vs[0];
        for (int i = 1; i < COUT; i++) { mx = fmaxf(mx, vs[i]); mn = fminf(mn, vs[i]); }
        vmm[0] = mx; vmm[1] = mn;
    }
    __syncthreads();

    {
        float kk = ks[tid];
        float m = (kk >= 0.f) ? kk * vmm[0] : kk * vmm[1];
        float r = 0.f;
        for (int e = 0; e < COUT; e++) r += expf(fmaf(kk, vs[e], -m));
        ms[tid] = m;
        invr[tid] = 1.f / r;
    }
    __syncthreads();

    float ve = vs[tid];
    float csum = 0.f;
    for (int o = 0; o < COUT; o++)
        csum += expf(fmaf(ks[o], ve, -ms[o])) * invr[o];
    float cinv = 1.f / (1e-9f + csum);

    __half* Ahb = d_Ah + (size_t)b * (COUT * COUT);
    __half* Alb = d_Al + (size_t)b * (COUT * COUT);
    for (int o = 0; o < COUT; o++) {
        float a = expf(fmaf(ks[o], ve, -ms[o])) * invr[o] * cinv;
        __half h = __float2half_rn(a);
        Ahb[o * COUT + tid] = h;
        Alb[o * COUT + tid] = __float2half_rn(a - __half2float(h));
    }
}

// biasv: [b_layer | b_tc + (b_layer^T (I-A)) Wtc^T]
__global__ void k_bc(const float* __restrict__ b_layer, const float* __restrict__ b_tc) {
    int b = blockIdx.x, e = threadIdx.x;
    __shared__ float v[COUT];
    const __half* Ahb = d_Ah + (size_t)b * (COUT * COUT);
    const __half* Alb = d_Al + (size_t)b * (COUT * COUT);
    float s = 0.f;
    for (int o = 0; o < COUT; o++) {
        float a = __half2float(Ahb[o * COUT + e]) + __half2float(Alb[o * COUT + e]);
        s = fmaf(b_layer[o], a, s);
    }
    v[e] = b_layer[e] - s;
    __syncthreads();
    float s2 = b_tc[e];
    for (int k = 0; k < COUT; k++) s2 = fmaf(v[k], d_WtcT[k * COUT + e], s2);
    d_biasv[b * 512 + e] = b_layer[e];
    d_biasv[b * 512 + 256 + e] = s2;
}

// ---------------- BN stats from partials ----------------
__global__ void k_bnstats2() {
    int n = blockIdx.x * 256 + threadIdx.x;
    float s = 0.f, q = 0.f;
    #pragma unroll
    for (int t = 0; t < 2 * NB; t++) {
        s += d_ps[(size_t)t * NN + n];
        q += d_pq[(size_t)t * NN + n];
    }
    float mean = s * (1.f / 8192.f);
    float var  = q * (1.f / 8192.f) - mean * mean;
    d_mean[n] = mean;
    d_rstd[n] = rsqrtf(var + 1e-5f);
}

// ---------------- epilogue (float4) ----------------
__global__ void k_final(const float* __restrict__ gamma, const float* __restrict__ beta,
                        float* __restrict__ out)
{
    int idx = blockIdx.x * 256 + threadIdx.x;    // handles 4 elems
    int e4 = (idx & 63) << 2;
    int n = (idx >> 6) & (NN - 1);
    int b = idx >> 17;
    size_t ybase = (size_t)b * (NN * 512) + (size_t)n * 512;
    float4 x1 = *(const float4*)(d_Y + ybase + e4);
    float4 tv = *(const float4*)(d_Y + ybase + 256 + e4);
    float4 gt = *(const float4*)(d_gate + b * COUT + e4);
    float4 hb = *(const float4*)(d_hbias + b * COUT + e4);
    float mr = d_mean[n], rs = d_rstd[n];
    float gm = gamma[n], bt = beta[n];
    float4 o;
    float bn;
    bn = fmaxf(fmaf((tv.x - mr) * rs, gm, bt), 0.f); o.x = fmaf(x1.x + bn, gt.x, hb.x);
    bn = fmaxf(fmaf((tv.y - mr) * rs, gm, bt), 0.f); o.y = fmaf(x1.y + bn, gt.y, hb.y);
    bn = fmaxf(fmaf((tv.z - mr) * rs, gm, bt), 0.f); o.z = fmaf(x1.z + bn, gt.z, hb.z);
    bn = fmaxf(fmaf((tv.w - mr) * rs, gm, bt), 0.f); o.w = fmaf(x1.w + bn, gt.w, hb.w);
    *(float4*)(out + (size_t)idx * 4) = o;
}

// ---------------- launch ----------------
extern "C" void kernel_launch(void* const* d_in, const int* in_sizes, int n_in,
                              void* d_out, int out_size)
{
    (void)in_sizes; (void)n_in; (void)out_size;
    const float* ctx     = (const float*)d_in[0];
    const float* x       = (const float*)d_in[1];
    const float* W_layer = (const float*)d_in[2];
    const float* b_layer = (const float*)d_in[3];
    const float* W_hbias = (const float*)d_in[4];
    const float* W_gate  = (const float*)d_in[5];
    const float* b_gate  = (const float*)d_in[6];
    const float* W_k     = (const float*)d_in[7];
    const float* W_v     = (const float*)d_in[8];
    const float* W_tc    = (const float*)d_in[9];
    const float* b_tc    = (const float*)d_in[10];
    const float* gamma   = (const float*)d_in[11];
    const float* beta    = (const float*)d_in[12];
    float* out = (float*)d_out;

    static int smem_set = 0;
    if (!smem_set) {
        cudaFuncSetAttribute(k_gemm_main_mma,
                             cudaFuncAttributeMaxDynamicSharedMemorySize, SMEM_MMA_BYTES);
        cudaFuncSetAttribute(k_gemm_Et,
                             cudaFuncAttributeMaxDynamicSharedMemorySize, SMEM_TS_BYTES);
        cudaFuncSetAttribute(k_gemm_D2,
                             cudaFuncAttributeMaxDynamicSharedMemorySize, SMEM_TS_BYTES);
        smem_set = 1;
    }

    k_transpose<<<dim3(256, 2), 256>>>(W_layer, W_tc);
    k_convx<<<(MTOT * CIN) / 1024, 256>>>(x);
    k_s1<<<NB, 256>>>(ctx, W_gate, b_gate, W_hbias, W_k, W_v);
    k_gemm_Et<<<dim3(2, 1, NB + 1), 256, SMEM_TS_BYTES>>>();
    k_gemm_D2<<<dim3(2, 1, NB), 256, SMEM_TS_BYTES>>>();
    k_bc<<<NB, 256>>>(b_layer, b_tc);
    k_gemm_main_mma<<<dim3(MTOT / 128, 4), 256, SMEM_MMA_BYTES>>>();
    k_bnstats2<<<NN / 256, 256>>>();
    k_final<<<(MTOT * COUT) / 1024, 256>>>(gamma, beta, out);
}